// round 2
// baseline (speedup 1.0000x reference)
#include <cuda_runtime.h>
#include <math_constants.h>

// ---------------------------------------------------------------------------
// ModifiedGAT: 3-layer GAT (PyG GATConv semantics, add_self_loops=True)
//   L0: IN=256 -> H=4 x OUT=64, concat -> 256, ELU
//   L1: 256 -> 64, heads=1, ELU
//   L2: 64 -> 64, heads=1, ELU  -> output [N,64] fp32
// ---------------------------------------------------------------------------

#define NMAX   50000
#define INCH   256
#define OUTC   64

// Scratch (device globals; no allocations allowed)
__device__ float g_h   [NMAX * 256];   // per-layer transformed features h = x @ W
__device__ float g_agg [NMAX * 256];   // numerator accumulation
__device__ float g_act [NMAX * 256];   // layer activation output (input to next layer)
__device__ float g_als [NMAX * 4];     // alpha_src logits per (node, head)
__device__ float g_ald [NMAX * 4];     // alpha_dst logits per (node, head)
__device__ float g_m   [NMAX * 4];     // segment max per (node, head)
__device__ float g_den [NMAX * 4];     // softmax denominator per (node, head)

// float atomic max via monotone int/uint mapping
__device__ __forceinline__ void atomicMaxF(float* addr, float v) {
    if (v >= 0.f) atomicMax((int*)addr, __float_as_int(v));
    else          atomicMin((unsigned int*)addr, __float_as_uint(v));
}

// ---------------------------------------------------------------------------
// init: zero agg [n*HOUT], zero den, set m = -inf  [n*Hh]
template<int HOUT, int Hh>
__global__ void init_k(int n) {
    int i = blockIdx.x * blockDim.x + threadIdx.x;
    if (i < n * HOUT) g_agg[i] = 0.f;
    if (i < n * Hh) {
        g_den[i] = 0.f;
        g_m[i]   = -CUDART_INF_F;
    }
}

// ---------------------------------------------------------------------------
// GEMM: g_h[row, 0:KOUT] = A[row, 0:M] @ W[M, KOUT]
// one node-row per block, blockDim = KOUT, W rows streamed from L2.
template<int M, int KOUT, bool IN_IS_X>
__global__ void gemm_k(const float* __restrict__ x, const float* __restrict__ W) {
    __shared__ float xs[M];
    const int row = blockIdx.x;
    const float* A = IN_IS_X ? x : g_act;
    const float* a = A + (size_t)row * M;
    for (int i = threadIdx.x; i < M; i += KOUT) xs[i] = a[i];
    __syncthreads();
    const int col = threadIdx.x;
    float acc0 = 0.f, acc1 = 0.f, acc2 = 0.f, acc3 = 0.f;
#pragma unroll 8
    for (int k = 0; k < M; k += 4) {
        acc0 += xs[k + 0] * W[(k + 0) * KOUT + col];
        acc1 += xs[k + 1] * W[(k + 1) * KOUT + col];
        acc2 += xs[k + 2] * W[(k + 2) * KOUT + col];
        acc3 += xs[k + 3] * W[(k + 3) * KOUT + col];
    }
    g_h[(size_t)row * KOUT + col] = (acc0 + acc1) + (acc2 + acc3);
}

// ---------------------------------------------------------------------------
// attention logits: one warp per (node, head); C=64 channels
template<int Hh>
__global__ void attn_logits_k(const float* __restrict__ a_s,
                              const float* __restrict__ a_d, int n) {
    int warp = (blockIdx.x * blockDim.x + threadIdx.x) >> 5;
    int lane = threadIdx.x & 31;
    if (warp >= n * Hh) return;
    int head = warp % Hh;                        // layout [n][h] == warp index
    const float* hp = g_h + (size_t)warp * OUTC; // (node*Hh + head)*64
    float s = 0.f, d = 0.f;
#pragma unroll
    for (int c = lane; c < OUTC; c += 32) {
        float v = hp[c];
        s += v * a_s[head * OUTC + c];
        d += v * a_d[head * OUTC + c];
    }
#pragma unroll
    for (int o = 16; o; o >>= 1) {
        s += __shfl_down_sync(0xffffffffu, s, o);
        d += __shfl_down_sync(0xffffffffu, d, o);
    }
    if (lane == 0) { g_als[warp] = s; g_ald[warp] = d; }
}

// ---------------------------------------------------------------------------
// edge pass 1: segment max over dst per head
template<int Hh>
__global__ void edge_max_k(const int* __restrict__ ei, int E, int Etot) {
    int i = blockIdx.x * blockDim.x + threadIdx.x;
    if (i >= Etot * Hh) return;
    int e  = i / Hh;
    int hh = i - e * Hh;
    int s, d;
    if (e >= E) { s = e - E; d = s; }
    else        { s = ei[e]; d = ei[E + e]; }
    float v = g_als[s * Hh + hh] + g_ald[d * Hh + hh];
    v = v > 0.f ? v : 0.2f * v;                  // leaky_relu(0.2)
    atomicMaxF(&g_m[d * Hh + hh], v);
}

// ---------------------------------------------------------------------------
// edge pass 2: ex = exp(leaky(...) - m[dst]); den += ex; agg[dst] += ex*h[src]
// exp computed ONCE per (edge,head) into shared, then channel scatter.
template<int HOUT, int Hh>
__global__ void edge_accum_k(const int* __restrict__ ei, int E, int Etot) {
    constexpr int EPB = 8192 / HOUT;             // 32 @HOUT=256, 128 @HOUT=64
    __shared__ int   ss[EPB], sd[EPB];
    __shared__ float sex[EPB * Hh];
    const int base = blockIdx.x * EPB;

    for (int t = threadIdx.x; t < EPB; t += blockDim.x) {
        int e = base + t;
        int s = -1, d = -1;
        if (e < Etot) {
            if (e >= E) { s = e - E; d = s; }
            else        { s = ei[e]; d = ei[E + e]; }
        }
        ss[t] = s; sd[t] = d;
    }
    __syncthreads();

    for (int t = threadIdx.x; t < EPB * Hh; t += blockDim.x) {
        int le = t / Hh;
        int hh = t - le * Hh;
        int s = ss[le], d = sd[le];
        float ex = 0.f;
        if (s >= 0) {
            float v = g_als[s * Hh + hh] + g_ald[d * Hh + hh];
            v  = v > 0.f ? v : 0.2f * v;
            ex = __expf(v - g_m[d * Hh + hh]);
            atomicAdd(&g_den[d * Hh + hh], ex);
        }
        sex[t] = ex;
    }
    __syncthreads();

    for (int t = threadIdx.x; t < EPB * HOUT; t += blockDim.x) {
        int le = t / HOUT;
        int ch = t - le * HOUT;
        int s = ss[le];
        if (s < 0) continue;
        int d  = sd[le];
        int hh = (Hh == 1) ? 0 : (ch >> 6);
        float ex = sex[le * Hh + hh];
        atomicAdd(&g_agg[(size_t)d * HOUT + ch],
                  ex * g_h[(size_t)s * HOUT + ch]);
    }
}

// ---------------------------------------------------------------------------
// finalize: out = elu(agg/(den+1e-16) + bias)
template<int HOUT, int Hh, bool TO_DOUT>
__global__ void finalize_k(const float* __restrict__ bias, float* __restrict__ dout, int n) {
    int i = blockIdx.x * blockDim.x + threadIdx.x;
    if (i >= n * HOUT) return;
    int node = i / HOUT;
    int ch   = i - node * HOUT;
    int hh   = (Hh == 1) ? 0 : (ch >> 6);
    float v = g_agg[i] / (g_den[node * Hh + hh] + 1e-16f) + bias[ch];
    v = v > 0.f ? v : (expf(v) - 1.f);           // ELU
    if (TO_DOUT) dout[i] = v;
    else         g_act[i] = v;
}

// ---------------------------------------------------------------------------
static inline int cdiv(int a, int b) { return (a + b - 1) / b; }

extern "C" void kernel_launch(void* const* d_in, const int* in_sizes, int n_in,
                              void* d_out, int out_size) {
    const float* x    = (const float*)d_in[0];
    const int*   ei   = (const int*)  d_in[1];
    const float* W0   = (const float*)d_in[2];
    const float* as0  = (const float*)d_in[3];
    const float* ad0  = (const float*)d_in[4];
    const float* b0   = (const float*)d_in[5];
    const float* W1   = (const float*)d_in[6];
    const float* as1  = (const float*)d_in[7];
    const float* ad1  = (const float*)d_in[8];
    const float* b1   = (const float*)d_in[9];
    const float* W2   = (const float*)d_in[10];
    const float* as2  = (const float*)d_in[11];
    const float* ad2  = (const float*)d_in[12];
    const float* b2   = (const float*)d_in[13];
    float* out = (float*)d_out;

    const int n    = in_sizes[0] / INCH;     // 50000
    const int E    = in_sizes[1] / 2;        // 800000
    const int Etot = E + n;                  // + self loops

    // ---------------- Layer 0: 256 -> 4x64 concat ----------------
    init_k<256, 4><<<cdiv(n * 256, 256), 256>>>(n);
    gemm_k<256, 256, true><<<n, 256>>>(x, W0);
    attn_logits_k<4><<<cdiv(n * 4 * 32, 256), 256>>>(as0, ad0, n);
    edge_max_k<4><<<cdiv(Etot * 4, 256), 256>>>(ei, E, Etot);
    edge_accum_k<256, 4><<<cdiv(Etot, 32), 256>>>(ei, E, Etot);
    finalize_k<256, 4, false><<<cdiv(n * 256, 256), 256>>>(b0, out, n);

    // ---------------- Layer 1: 256 -> 64, heads=1 ----------------
    init_k<64, 1><<<cdiv(n * 64, 256), 256>>>(n);
    gemm_k<256, 64, false><<<n, 64>>>(x, W1);
    attn_logits_k<1><<<cdiv(n * 32, 256), 256>>>(as1, ad1, n);
    edge_max_k<1><<<cdiv(Etot, 256), 256>>>(ei, E, Etot);
    edge_accum_k<64, 1><<<cdiv(Etot, 128), 256>>>(ei, E, Etot);
    finalize_k<64, 1, false><<<cdiv(n * 64, 256), 256>>>(b1, out, n);

    // ---------------- Layer 2: 64 -> 64, heads=1 -----------------
    init_k<64, 1><<<cdiv(n * 64, 256), 256>>>(n);
    gemm_k<64, 64, false><<<n, 64>>>(x, W2);
    attn_logits_k<1><<<cdiv(n * 32, 256), 256>>>(as2, ad2, n);
    edge_max_k<1><<<cdiv(Etot, 256), 256>>>(ei, E, Etot);
    edge_accum_k<64, 1><<<cdiv(Etot, 128), 256>>>(ei, E, Etot);
    finalize_k<64, 1, true><<<cdiv(n * 64, 256), 256>>>(b2, out, n);
}

// round 3
// speedup vs baseline: 2.0814x; 2.0814x over previous
#include <cuda_runtime.h>
#include <math_constants.h>

// ---------------------------------------------------------------------------
// ModifiedGAT: 3-layer GAT (PyG GATConv, add_self_loops=True)
//   L0: 256 -> 4x64 concat=256, ELU;  L1: 256 -> 64, ELU;  L2: 64 -> 64, ELU
// CSR-gather formulation: no feature atomics, no init/finalize passes.
// ---------------------------------------------------------------------------

#define NMAX   50000
#define EMAX   850000   // 800000 edges + 50000 self loops
#define INCH   256
#define OUTC   64

// Scratch (device globals; allocations are forbidden)
__device__ float g_h   [NMAX * 256];   // transformed features h = x @ W
__device__ float g_act [NMAX * 256];   // layer activation (input to next layer)
__device__ float g_als [NMAX * 4];     // alpha_src logits per (node, head)
__device__ float g_ald [NMAX * 4];     // alpha_dst logits per (node, head)
__device__ int   g_cnt [NMAX];         // degree counts -> fill cursors
__device__ int   g_off [NMAX + 1];     // CSR offsets (by dst)
__device__ int   g_csr [EMAX];         // src node per CSR slot

static inline int cdiv(int a, int b) { return (a + b - 1) / b; }

// ---------------------------------------------------------------------------
// CSR build
__global__ void csr_zero_k(int n) {
    int i = blockIdx.x * blockDim.x + threadIdx.x;
    if (i < n) g_cnt[i] = 0;
}

__global__ void csr_count_k(const int* __restrict__ ei, int E, int Etot) {
    int i = blockIdx.x * blockDim.x + threadIdx.x;
    if (i >= Etot) return;
    int d = (i < E) ? ei[E + i] : (i - E);
    atomicAdd(&g_cnt[d], 1);
}

// single-block exclusive scan over g_cnt -> g_off, cursor copy into g_cnt
__global__ void csr_scan_k(int n, int Etot) {
    __shared__ int sh[32];
    __shared__ int carry;
    const int t = threadIdx.x;            // 1024 threads
    const int lane = t & 31, w = t >> 5;
    if (t == 0) carry = 0;
    __syncthreads();
    for (int base = 0; base < n; base += 1024) {
        int i = base + t;
        int v = (i < n) ? g_cnt[i] : 0;
        // warp inclusive scan
        int x = v;
#pragma unroll
        for (int o = 1; o < 32; o <<= 1) {
            int y = __shfl_up_sync(0xffffffffu, x, o);
            if (lane >= o) x += y;
        }
        if (lane == 31) sh[w] = x;
        __syncthreads();
        if (w == 0) {
            int y = sh[lane];
#pragma unroll
            for (int o = 1; o < 32; o <<= 1) {
                int z = __shfl_up_sync(0xffffffffu, y, o);
                if (lane >= o) y += z;
            }
            sh[lane] = y;
        }
        __syncthreads();
        int incl = x + ((w == 0) ? 0 : sh[w - 1]);
        int excl = incl - v;
        if (i < n) { g_off[i] = carry + excl; g_cnt[i] = carry + excl; }
        __syncthreads();
        if (t == 1023) carry += incl;
        __syncthreads();
    }
    if (t == 0) g_off[n] = Etot;
}

__global__ void csr_fill_k(const int* __restrict__ ei, int E, int Etot) {
    int i = blockIdx.x * blockDim.x + threadIdx.x;
    if (i >= Etot) return;
    int s, d;
    if (i < E) { s = ei[i]; d = ei[E + i]; }
    else       { s = i - E; d = s; }
    int pos = atomicAdd(&g_cnt[d], 1);
    g_csr[pos] = s;
}

// ---------------------------------------------------------------------------
// GEMM: g_h[r, :KOUT] = A[r, :M] @ W[M, KOUT], R rows per block.
// blockDim = KOUT threads (one output column each); W element reused R times.
template<int M, int KOUT, int R, bool IN_IS_X>
__global__ void gemm_k(const float* __restrict__ x, const float* __restrict__ W, int n) {
    __shared__ float xs[R][M];
    const int col = threadIdx.x;
    const int r0 = blockIdx.x * R;
    const float* A = IN_IS_X ? x : g_act;

    const float4* Av = (const float4*)(A + (size_t)r0 * M);
    float4* xv = (float4*)&xs[0][0];
    for (int i = threadIdx.x; i < R * M / 4; i += KOUT) xv[i] = Av[i];
    __syncthreads();

    float acc[R];
#pragma unroll
    for (int r = 0; r < R; r++) acc[r] = 0.f;

#pragma unroll 4
    for (int k = 0; k < M; k += 4) {
        float w0 = W[(k + 0) * KOUT + col];
        float w1 = W[(k + 1) * KOUT + col];
        float w2 = W[(k + 2) * KOUT + col];
        float w3 = W[(k + 3) * KOUT + col];
#pragma unroll
        for (int r = 0; r < R; r++) {
            float4 a = *(const float4*)&xs[r][k];
            acc[r] += a.x * w0;
            acc[r] += a.y * w1;
            acc[r] += a.z * w2;
            acc[r] += a.w * w3;
        }
    }
#pragma unroll
    for (int r = 0; r < R; r++)
        g_h[(size_t)(r0 + r) * KOUT + col] = acc[r];
}

// ---------------------------------------------------------------------------
// attention logits: one warp per (node, head)
template<int Hh>
__global__ void attn_logits_k(const float* __restrict__ a_s,
                              const float* __restrict__ a_d, int n) {
    int warp = (blockIdx.x * blockDim.x + threadIdx.x) >> 5;
    int lane = threadIdx.x & 31;
    if (warp >= n * Hh) return;
    int head = warp % Hh;
    const float* hp = g_h + (size_t)warp * OUTC;
    float s = 0.f, d = 0.f;
#pragma unroll
    for (int c = lane; c < OUTC; c += 32) {
        float v = hp[c];
        s += v * a_s[head * OUTC + c];
        d += v * a_d[head * OUTC + c];
    }
#pragma unroll
    for (int o = 16; o; o >>= 1) {
        s += __shfl_down_sync(0xffffffffu, s, o);
        d += __shfl_down_sync(0xffffffffu, d, o);
    }
    if (lane == 0) { g_als[warp] = s; g_ald[warp] = d; }
}

// ---------------------------------------------------------------------------
// Fused per-dst aggregation: max -> softmax -> weighted gather -> bias+ELU.
// One warp per destination node. No atomics.
template<int HOUT, int Hh, bool TO_OUT>
__global__ void aggr_k(const float* __restrict__ bias, float* __restrict__ outp, int n) {
    const int warp = (blockIdx.x * blockDim.x + threadIdx.x) >> 5;
    const int lane = threadIdx.x & 31;
    if (warp >= n) return;
    const int dst = warp;
    const int beg = g_off[dst], end = g_off[dst + 1];
    constexpr int K = HOUT / 32;            // channels per lane (8 or 2)

    float aldd[Hh];
#pragma unroll
    for (int h = 0; h < Hh; h++) aldd[h] = g_ald[dst * Hh + h];

    // pass A: per-head segment max
    float mx[Hh];
#pragma unroll
    for (int h = 0; h < Hh; h++) mx[h] = -CUDART_INF_F;
    for (int e = beg + lane; e < end; e += 32) {
        int s = g_csr[e];
#pragma unroll
        for (int h = 0; h < Hh; h++) {
            float v = g_als[s * Hh + h] + aldd[h];
            v = v > 0.f ? v : 0.2f * v;
            mx[h] = fmaxf(mx[h], v);
        }
    }
#pragma unroll
    for (int o = 16; o; o >>= 1)
#pragma unroll
        for (int h = 0; h < Hh; h++)
            mx[h] = fmaxf(mx[h], __shfl_xor_sync(0xffffffffu, mx[h], o));

    // static lane-indexed selects (avoid local-memory spill)
    float mx_own, ald_own;
    if (Hh == 4) {
        mx_own  = (lane & 2) ? ((lane & 1) ? mx[3]   : mx[2])
                             : ((lane & 1) ? mx[1]   : mx[0]);
        ald_own = (lane & 2) ? ((lane & 1) ? aldd[3] : aldd[2])
                             : ((lane & 1) ? aldd[1] : aldd[0]);
    } else {
        mx_own = mx[0]; ald_own = aldd[0];
    }

    // pass B: exp once per (edge, head) on lanes 0..Hh-1, broadcast to channels
    float acc[K];
#pragma unroll
    for (int k = 0; k < K; k++) acc[k] = 0.f;
    float den = 0.f;                        // lane h accumulates head h's denom

    for (int e = beg; e < end; e++) {
        int s = g_csr[e];                   // uniform across warp
        float exh = 0.f;
        if (lane < Hh) {
            float v = g_als[s * Hh + lane] + ald_own;
            v = v > 0.f ? v : 0.2f * v;
            exh = __expf(v - mx_own);
            den += exh;
        }
        const float* hs = g_h + (size_t)s * HOUT;
#pragma unroll
        for (int k = 0; k < K; k++) {
            float ex = __shfl_sync(0xffffffffu, exh, (Hh == 1) ? 0 : (k >> 1));
            acc[k] += ex * hs[lane + 32 * k];
        }
    }

    // finalize: divide, bias, ELU, store
#pragma unroll
    for (int k = 0; k < K; k++) {
        const int head = (Hh == 1) ? 0 : (k >> 1);
        float dv = __shfl_sync(0xffffffffu, den, head);
        int ch = lane + 32 * k;
        float v = acc[k] / (dv + 1e-16f) + bias[ch];
        v = v > 0.f ? v : expm1f(v);
        float* o = TO_OUT ? outp : g_act;
        o[(size_t)dst * HOUT + ch] = v;
    }
}

// ---------------------------------------------------------------------------
extern "C" void kernel_launch(void* const* d_in, const int* in_sizes, int n_in,
                              void* d_out, int out_size) {
    const float* x    = (const float*)d_in[0];
    const int*   ei   = (const int*)  d_in[1];
    const float* W0   = (const float*)d_in[2];
    const float* as0  = (const float*)d_in[3];
    const float* ad0  = (const float*)d_in[4];
    const float* b0   = (const float*)d_in[5];
    const float* W1   = (const float*)d_in[6];
    const float* as1  = (const float*)d_in[7];
    const float* ad1  = (const float*)d_in[8];
    const float* b1   = (const float*)d_in[9];
    const float* W2   = (const float*)d_in[10];
    const float* as2  = (const float*)d_in[11];
    const float* ad2  = (const float*)d_in[12];
    const float* b2   = (const float*)d_in[13];
    float* out = (float*)d_out;

    const int n    = in_sizes[0] / INCH;   // 50000
    const int E    = in_sizes[1] / 2;      // 800000
    const int Etot = E + n;                // + self loops

    // ---- CSR build (once; shared by all 3 layers) ----
    csr_zero_k <<<cdiv(n, 256), 256>>>(n);
    csr_count_k<<<cdiv(Etot, 256), 256>>>(ei, E, Etot);
    csr_scan_k <<<1, 1024>>>(n, Etot);
    csr_fill_k <<<cdiv(Etot, 256), 256>>>(ei, E, Etot);

    // ---- Layer 0: 256 -> 4x64 concat ----
    gemm_k<256, 256, 8, true><<<cdiv(n, 8), 256>>>(x, W0, n);
    attn_logits_k<4><<<cdiv(n * 4 * 32, 256), 256>>>(as0, ad0, n);
    aggr_k<256, 4, false><<<cdiv(n * 32, 256), 256>>>(b0, out, n);

    // ---- Layer 1: 256 -> 64 ----
    gemm_k<256, 64, 8, false><<<cdiv(n, 8), 64>>>(x, W1, n);
    attn_logits_k<1><<<cdiv(n * 32, 256), 256>>>(as1, ad1, n);
    aggr_k<64, 1, false><<<cdiv(n * 32, 256), 256>>>(b1, out, n);

    // ---- Layer 2: 64 -> 64 ----
    gemm_k<64, 64, 8, false><<<cdiv(n, 8), 64>>>(x, W2, n);
    attn_logits_k<1><<<cdiv(n * 32, 256), 256>>>(as2, ad2, n);
    aggr_k<64, 1, true><<<cdiv(n * 32, 256), 256>>>(b2, out, n);
}

// round 6
// speedup vs baseline: 2.7532x; 1.3227x over previous
#include <cuda_runtime.h>
#include <cuda_bf16.h>
#include <math_constants.h>
#include <cstdint>

// ---------------------------------------------------------------------------
// ModifiedGAT: 3-layer GAT (PyG GATConv, add_self_loops=True)
//   L0: 256 -> 4x64 concat=256, ELU;  L1: 256 -> 64, ELU;  L2: 64 -> 64, ELU
// CSR-gather aggregation + split-bf16 HMMA (mma.sync) GEMMs.
// ---------------------------------------------------------------------------

#define NMAX   50000
#define EMAX   850000
#define INCH   256
#define OUTC   64

__device__ float g_h   [NMAX * 256];          // GEMM output (fp32)
__device__ float g_als [NMAX * 4];
__device__ float g_ald [NMAX * 4];
__device__ int   g_cnt [NMAX];
__device__ int   g_off [NMAX + 1];
__device__ int   g_csr [EMAX];
__device__ __nv_bfloat16 g_ext [NMAX * 512];  // hi|lo bf16 GEMM input (stride 2*KIN)
__device__ __nv_bfloat16 g_wext[4 * 64 * 512]; // Bt_ext [tile][n=64][kext] bf16

static inline int cdiv(int a, int b) { return (a + b - 1) / b; }

__device__ __forceinline__ uint32_t pk(__nv_bfloat16 a, __nv_bfloat16 b) {
    return (uint32_t)__bfloat16_as_ushort(a) | ((uint32_t)__bfloat16_as_ushort(b) << 16);
}

// ------------------------------- CSR build ---------------------------------
__global__ void csr_zero_k(int n) {
    int i = blockIdx.x * blockDim.x + threadIdx.x;
    if (i < n) g_cnt[i] = 0;
}
__global__ void csr_count_k(const int* __restrict__ ei, int E, int Etot) {
    int i = blockIdx.x * blockDim.x + threadIdx.x;
    if (i >= Etot) return;
    int d = (i < E) ? ei[E + i] : (i - E);
    atomicAdd(&g_cnt[d], 1);
}
__global__ void csr_scan_k(int n, int Etot) {
    __shared__ int sh[32];
    __shared__ int carry;
    const int t = threadIdx.x, lane = t & 31, w = t >> 5;
    if (t == 0) carry = 0;
    __syncthreads();
    for (int base = 0; base < n; base += 1024) {
        int i = base + t;
        int v = (i < n) ? g_cnt[i] : 0;
        int x = v;
#pragma unroll
        for (int o = 1; o < 32; o <<= 1) {
            int y = __shfl_up_sync(0xffffffffu, x, o);
            if (lane >= o) x += y;
        }
        if (lane == 31) sh[w] = x;
        __syncthreads();
        if (w == 0) {
            int y = sh[lane];
#pragma unroll
            for (int o = 1; o < 32; o <<= 1) {
                int z = __shfl_up_sync(0xffffffffu, y, o);
                if (lane >= o) y += z;
            }
            sh[lane] = y;
        }
        __syncthreads();
        int incl = x + ((w == 0) ? 0 : sh[w - 1]);
        int excl = incl - v;
        if (i < n) { g_off[i] = carry + excl; g_cnt[i] = carry + excl; }
        __syncthreads();
        if (t == 1023) carry += incl;
        __syncthreads();
    }
    if (t == 0) g_off[n] = Etot;
}
__global__ void csr_fill_k(const int* __restrict__ ei, int E, int Etot) {
    int i = blockIdx.x * blockDim.x + threadIdx.x;
    if (i >= Etot) return;
    int s, d;
    if (i < E) { s = ei[i]; d = ei[E + i]; }
    else       { s = i - E; d = s; }
    int pos = atomicAdd(&g_cnt[d], 1);
    g_csr[pos] = s;
}

// ---------------- fp32 -> (hi|lo) bf16 extension (for x) -------------------
template<int KIN>
__global__ void ext_from_f32_k(const float* __restrict__ src, int n) {
    constexpr int Q = KIN / 4;
    int idx = blockIdx.x * blockDim.x + threadIdx.x;
    if (idx >= n * Q) return;
    int row = idx / Q, q = idx - row * Q;
    float4 v = ((const float4*)src)[idx];
    __nv_bfloat16 h0 = __float2bfloat16_rn(v.x), h1 = __float2bfloat16_rn(v.y);
    __nv_bfloat16 h2 = __float2bfloat16_rn(v.z), h3 = __float2bfloat16_rn(v.w);
    __nv_bfloat16 l0 = __float2bfloat16_rn(v.x - __bfloat162float(h0));
    __nv_bfloat16 l1 = __float2bfloat16_rn(v.y - __bfloat162float(h1));
    __nv_bfloat16 l2 = __float2bfloat16_rn(v.z - __bfloat162float(h2));
    __nv_bfloat16 l3 = __float2bfloat16_rn(v.w - __bfloat162float(h3));
    __nv_bfloat16* d = g_ext + (size_t)row * (2 * KIN) + 4 * q;
    *(uint2*)d             = make_uint2(pk(h0, h1), pk(h2, h3));
    *(uint2*)(d + KIN)     = make_uint2(pk(l0, l1), pk(l2, l3));
}

// ----------------- W -> Bt_ext [tile][n][kext] bf16 hi|lo ------------------
__global__ void wext_k(const float* __restrict__ W, int stride, int KIN, int T) {
    int total = T * 64 * (KIN / 2);
    int idx = blockIdx.x * blockDim.x + threadIdx.x;
    if (idx >= total) return;
    int nn   = idx & 63;
    int rest = idx >> 6;
    int kp   = rest % (KIN / 2);
    int t    = rest / (KIN / 2);
    int k0   = kp * 2;
    int col  = t * 64 + nn;
    float w0 = W[(size_t)k0 * stride + col];
    float w1 = W[(size_t)(k0 + 1) * stride + col];
    __nv_bfloat16 h0 = __float2bfloat16_rn(w0);
    __nv_bfloat16 h1 = __float2bfloat16_rn(w1);
    __nv_bfloat16 l0 = __float2bfloat16_rn(w0 - __bfloat162float(h0));
    __nv_bfloat16 l1 = __float2bfloat16_rn(w1 - __bfloat162float(h1));
    __nv_bfloat16* base = g_wext + ((size_t)t * 64 + nn) * (2 * KIN);
    *(uint32_t*)(base + k0)       = pk(h0, h1);
    *(uint32_t*)(base + KIN + k0) = pk(l0, l1);
}

// --------------------- split-bf16 HMMA GEMM (128x64 tile) ------------------
// C[128,64] = A[128,KIN] @ W[KIN, tile*64 .. +64]; segments hi*hi+lo*hi+hi*lo.
// 8 warps: warp w -> rows 16w..16w+15, all 64 cols. m16n8k16 fragments via LDS.
template<int KIN>
__global__ void __launch_bounds__(256, 1)
gemm_mma_k(int nrows, int noutTot) {
    constexpr int KEXT = 2 * KIN;
    constexpr int SA   = KEXT + 8;            // padded smem stride (elems)
    extern __shared__ __align__(16) __nv_bfloat16 sm[];
    __nv_bfloat16* As = sm;                   // [128][SA]
    __nv_bfloat16* Bs = sm + 128 * SA;        // [64][SA]
    const int tid = threadIdx.x, wid = tid >> 5, lane = tid & 31;
    const int r0 = blockIdx.x * 128;
    const int t  = blockIdx.y;

    constexpr int QA = KEXT / 8;              // uint4 per row
    for (int idx = tid; idx < 128 * QA; idx += 256) {
        int row = idx / QA, q = idx - row * QA;
        uint4 v = make_uint4(0u, 0u, 0u, 0u);
        if (r0 + row < nrows)
            v = ((const uint4*)(g_ext + (size_t)(r0 + row) * KEXT))[q];
        *(uint4*)(As + row * SA + q * 8) = v;
    }
    const __nv_bfloat16* Bg = g_wext + (size_t)t * 64 * KEXT;
    for (int idx = tid; idx < 64 * QA; idx += 256) {
        int row = idx / QA, q = idx - row * QA;
        uint4 v = ((const uint4*)(Bg + (size_t)row * KEXT))[q];
        *(uint4*)(Bs + row * SA + q * 8) = v;
    }
    __syncthreads();

    const int g  = lane >> 2, tq = lane & 3;
    const int mr = wid * 16;
    float c[8][4];
#pragma unroll
    for (int j = 0; j < 8; j++)
#pragma unroll
        for (int i = 0; i < 4; i++) c[j][i] = 0.f;

    const __nv_bfloat16* Ar0 = As + (mr + g) * SA + tq * 2;
    const __nv_bfloat16* Ar1 = Ar0 + 8 * SA;
    const __nv_bfloat16* Br  = Bs + g * SA + tq * 2;

#pragma unroll
    for (int sg = 0; sg < 3; sg++) {
        const int ak0 = (sg == 1) ? KIN : 0;
        const int bk0 = (sg == 2) ? KIN : 0;
#pragma unroll 2
        for (int ks = 0; ks < KIN / 16; ks++) {
            const int ak = ak0 + ks * 16;
            const int bk = bk0 + ks * 16;
            uint32_t a0 = *(const uint32_t*)(Ar0 + ak);
            uint32_t a1 = *(const uint32_t*)(Ar1 + ak);
            uint32_t a2 = *(const uint32_t*)(Ar0 + ak + 8);
            uint32_t a3 = *(const uint32_t*)(Ar1 + ak + 8);
#pragma unroll
            for (int j = 0; j < 8; j++) {
                uint32_t b0 = *(const uint32_t*)(Br + j * 8 * SA + bk);
                uint32_t b1 = *(const uint32_t*)(Br + j * 8 * SA + bk + 8);
                asm volatile(
                    "mma.sync.aligned.m16n8k16.row.col.f32.bf16.bf16.f32 "
                    "{%0,%1,%2,%3}, {%4,%5,%6,%7}, {%8,%9}, {%0,%1,%2,%3};"
                    : "+f"(c[j][0]), "+f"(c[j][1]), "+f"(c[j][2]), "+f"(c[j][3])
                    : "r"(a0), "r"(a1), "r"(a2), "r"(a3), "r"(b0), "r"(b1));
            }
        }
    }

    const int gr0 = r0 + mr + g, gr1 = gr0 + 8;
    float* H0 = g_h + (size_t)gr0 * noutTot + t * 64 + tq * 2;
    float* H1 = g_h + (size_t)gr1 * noutTot + t * 64 + tq * 2;
    if (gr0 < nrows) {
#pragma unroll
        for (int j = 0; j < 8; j++) *(float2*)(H0 + j * 8) = make_float2(c[j][0], c[j][1]);
    }
    if (gr1 < nrows) {
#pragma unroll
        for (int j = 0; j < 8; j++) *(float2*)(H1 + j * 8) = make_float2(c[j][2], c[j][3]);
    }
}

// --------------------------- attention logits ------------------------------
template<int Hh>
__global__ void attn_logits_k(const float* __restrict__ a_s,
                              const float* __restrict__ a_d, int n) {
    int warp = (blockIdx.x * blockDim.x + threadIdx.x) >> 5;
    int lane = threadIdx.x & 31;
    if (warp >= n * Hh) return;
    int head = warp % Hh;
    const float* hp = g_h + (size_t)warp * OUTC;
    float s = 0.f, d = 0.f;
#pragma unroll
    for (int c = lane; c < OUTC; c += 32) {
        float v = hp[c];
        s += v * a_s[head * OUTC + c];
        d += v * a_d[head * OUTC + c];
    }
#pragma unroll
    for (int o = 16; o; o >>= 1) {
        s += __shfl_down_sync(0xffffffffu, s, o);
        d += __shfl_down_sync(0xffffffffu, d, o);
    }
    if (lane == 0) { g_als[warp] = s; g_ald[warp] = d; }
}

// -------------------- fused per-dst softmax aggregation --------------------
// One warp per dst; lane owns V = HOUT/32 contiguous channels.
// MODE 0: write hi|lo bf16 ext (input of next GEMM). MODE 1: write fp32 out.
template<int HOUT, int Hh, int MODE>
__global__ void aggr_k(const float* __restrict__ bias, float* __restrict__ outp, int n) {
    const int warp = (blockIdx.x * blockDim.x + threadIdx.x) >> 5;
    const int lane = threadIdx.x & 31;
    if (warp >= n) return;
    const int dst = warp;
    const int beg = g_off[dst], end = g_off[dst + 1];
    constexpr int V = HOUT / 32;

    float aldd[Hh];
    if (Hh == 4) {
        float4 t = *(const float4*)(g_ald + dst * 4);
        aldd[0] = t.x; aldd[1] = t.y; aldd[2] = t.z; aldd[3] = t.w;
    } else aldd[0] = g_ald[dst];

    float mx[Hh];
#pragma unroll
    for (int h = 0; h < Hh; h++) mx[h] = -CUDART_INF_F;
    for (int e = beg + lane; e < end; e += 32) {
        int s = g_csr[e];
        if (Hh == 4) {
            float4 a = *(const float4*)(g_als + s * 4);
            float v0 = a.x + aldd[0]; v0 = v0 > 0.f ? v0 : 0.2f * v0; mx[0] = fmaxf(mx[0], v0);
            float v1 = a.y + aldd[1]; v1 = v1 > 0.f ? v1 : 0.2f * v1; mx[1] = fmaxf(mx[1], v1);
            float v2 = a.z + aldd[2]; v2 = v2 > 0.f ? v2 : 0.2f * v2; mx[2] = fmaxf(mx[2], v2);
            float v3 = a.w + aldd[3]; v3 = v3 > 0.f ? v3 : 0.2f * v3; mx[3] = fmaxf(mx[3], v3);
        } else {
            float v = g_als[s] + aldd[0]; v = v > 0.f ? v : 0.2f * v; mx[0] = fmaxf(mx[0], v);
        }
    }
#pragma unroll
    for (int o = 16; o; o >>= 1)
#pragma unroll
        for (int h = 0; h < Hh; h++)
            mx[h] = fmaxf(mx[h], __shfl_xor_sync(0xffffffffu, mx[h], o));

    float mx_own, ald_own;
    if (Hh == 4) {
        mx_own  = (lane & 2) ? ((lane & 1) ? mx[3]   : mx[2])
                             : ((lane & 1) ? mx[1]   : mx[0]);
        ald_own = (lane & 2) ? ((lane & 1) ? aldd[3] : aldd[2])
                             : ((lane & 1) ? aldd[1] : aldd[0]);
    } else { mx_own = mx[0]; ald_own = aldd[0]; }

    float acc[V];
#pragma unroll
    for (int k = 0; k < V; k++) acc[k] = 0.f;
    float den = 0.f;
    const int headL = (Hh == 1) ? 0 : (lane >> 3);

    for (int e = beg; e < end; e++) {
        int s = g_csr[e];
        float exh = 0.f;
        if (lane < Hh) {
            float v = g_als[s * Hh + lane] + ald_own;
            v = v > 0.f ? v : 0.2f * v;
            exh = __expf(v - mx_own);
            den += exh;
        }
        float ex = __shfl_sync(0xffffffffu, exh, headL);
        if (V == 8) {
            const float4* hs = (const float4*)(g_h + (size_t)s * HOUT);
            float4 p0 = hs[lane * 2], p1 = hs[lane * 2 + 1];
            acc[0] += ex * p0.x; acc[1] += ex * p0.y;
            acc[2] += ex * p0.z; acc[3] += ex * p0.w;
            acc[4] += ex * p1.x; acc[5] += ex * p1.y;
            acc[6] += ex * p1.z; acc[7] += ex * p1.w;
        } else {
            const float2* hs = (const float2*)(g_h + (size_t)s * HOUT);
            float2 p = hs[lane];
            acc[0] += ex * p.x; acc[1] += ex * p.y;
        }
    }

    float dv  = __shfl_sync(0xffffffffu, den, headL);
    float inv = 1.f / (dv + 1e-16f);
    float r[V];
    if (V == 8) {
        float4 b0 = *(const float4*)(bias + lane * 8);
        float4 b1 = *(const float4*)(bias + lane * 8 + 4);
        r[0] = acc[0] * inv + b0.x; r[1] = acc[1] * inv + b0.y;
        r[2] = acc[2] * inv + b0.z; r[3] = acc[3] * inv + b0.w;
        r[4] = acc[4] * inv + b1.x; r[5] = acc[5] * inv + b1.y;
        r[6] = acc[6] * inv + b1.z; r[7] = acc[7] * inv + b1.w;
    } else {
        float2 b = *(const float2*)(bias + lane * 2);
        r[0] = acc[0] * inv + b.x; r[1] = acc[1] * inv + b.y;
    }
#pragma unroll
    for (int j = 0; j < V; j++) r[j] = r[j] > 0.f ? r[j] : expm1f(r[j]);

    if (MODE == 1) {
        if (V == 2)
            *(float2*)(outp + (size_t)dst * HOUT + lane * 2) = make_float2(r[0], r[1]);
    } else {
        // hi|lo bf16 ext, stride KEXT = 2*HOUT
        __nv_bfloat16 hi[V], lo[V];
#pragma unroll
        for (int j = 0; j < V; j++) {
            hi[j] = __float2bfloat16_rn(r[j]);
            lo[j] = __float2bfloat16_rn(r[j] - __bfloat162float(hi[j]));
        }
        if (V == 8) {
            __nv_bfloat16* eb = g_ext + (size_t)dst * 512 + lane * 8;
            *(uint4*)eb         = make_uint4(pk(hi[0], hi[1]), pk(hi[2], hi[3]),
                                             pk(hi[4], hi[5]), pk(hi[6], hi[7]));
            *(uint4*)(eb + 256) = make_uint4(pk(lo[0], lo[1]), pk(lo[2], lo[3]),
                                             pk(lo[4], lo[5]), pk(lo[6], lo[7]));
        } else {
            __nv_bfloat16* eb = g_ext + (size_t)dst * 128 + lane * 2;
            *(uint32_t*)eb        = pk(hi[0], hi[1]);
            *(uint32_t*)(eb + 64) = pk(lo[0], lo[1]);
        }
    }
}

// ---------------------------------------------------------------------------
extern "C" void kernel_launch(void* const* d_in, const int* in_sizes, int n_in,
                              void* d_out, int out_size) {
    const float* x   = (const float*)d_in[0];
    const int*   ei  = (const int*)  d_in[1];
    const float* W0  = (const float*)d_in[2];
    const float* as0 = (const float*)d_in[3];
    const float* ad0 = (const float*)d_in[4];
    const float* b0  = (const float*)d_in[5];
    const float* W1  = (const float*)d_in[6];
    const float* as1 = (const float*)d_in[7];
    const float* ad1 = (const float*)d_in[8];
    const float* b1  = (const float*)d_in[9];
    const float* W2  = (const float*)d_in[10];
    const float* as2 = (const float*)d_in[11];
    const float* ad2 = (const float*)d_in[12];
    const float* b2  = (const float*)d_in[13];
    float* out = (float*)d_out;

    const int n    = in_sizes[0] / INCH;   // 50000
    const int E    = in_sizes[1] / 2;      // 800000
    const int Etot = E + n;

    const int SM256 = (128 + 64) * (512 + 8) * 2;   // 199,680 B
    const int SM64  = (128 + 64) * (128 + 8) * 2;   //  52,224 B
    cudaFuncSetAttribute(gemm_mma_k<256>, cudaFuncAttributeMaxDynamicSharedMemorySize, SM256);
    cudaFuncSetAttribute(gemm_mma_k<64>,  cudaFuncAttributeMaxDynamicSharedMemorySize, SM64);

    // ---- CSR build (shared by all layers) ----
    csr_zero_k <<<cdiv(n, 256), 256>>>(n);
    csr_count_k<<<cdiv(Etot, 256), 256>>>(ei, E, Etot);
    csr_scan_k <<<1, 1024>>>(n, Etot);
    csr_fill_k <<<cdiv(Etot, 256), 256>>>(ei, E, Etot);

    const int nb = cdiv(n, 128);

    // ---- Layer 0: 256 -> 4x64 concat ----
    ext_from_f32_k<256><<<cdiv(n * 64, 256), 256>>>(x, n);
    wext_k<<<cdiv(4 * 64 * 128, 256), 256>>>(W0, 256, 256, 4);
    gemm_mma_k<256><<<dim3(nb, 4), 256, SM256>>>(n, 256);
    attn_logits_k<4><<<cdiv(n * 4 * 32, 256), 256>>>(as0, ad0, n);
    aggr_k<256, 4, 0><<<cdiv(n * 32, 256), 256>>>(b0, out, n);

    // ---- Layer 1: 256 -> 64 ----
    wext_k<<<cdiv(1 * 64 * 128, 256), 256>>>(W1, 64, 256, 1);
    gemm_mma_k<256><<<dim3(nb, 1), 256, SM256>>>(n, 64);
    attn_logits_k<1><<<cdiv(n * 32, 256), 256>>>(as1, ad1, n);
    aggr_k<64, 1, 0><<<cdiv(n * 32, 256), 256>>>(b1, out, n);

    // ---- Layer 2: 64 -> 64 ----
    wext_k<<<cdiv(1 * 64 * 32, 256), 256>>>(W2, 64, 64, 1);
    gemm_mma_k<64><<<dim3(nb, 1), 256, SM64>>>(n, 64);
    attn_logits_k<1><<<cdiv(n * 32, 256), 256>>>(as2, ad2, n);
    aggr_k<64, 1, 1><<<cdiv(n * 32, 256), 256>>>(b2, out, n);
}

// round 7
// speedup vs baseline: 2.9436x; 1.0692x over previous
#include <cuda_runtime.h>
#include <cuda_bf16.h>
#include <math_constants.h>
#include <cstdint>

// ---------------------------------------------------------------------------
// ModifiedGAT: 3-layer GAT (PyG GATConv, add_self_loops=True)
//   L0: 256 -> 4x64 concat=256, ELU;  L1: 256 -> 64, ELU;  L2: 64 -> 64, ELU
// CSR-gather single-pass-softmax aggregation + split-bf16 HMMA GEMMs with
// fused attention-logit epilogue.
// ---------------------------------------------------------------------------

#define NMAX   50000
#define EMAX   850000
#define INCH   256
#define OUTC   64

__device__ float g_h   [NMAX * 256];           // GEMM output (fp32)
__device__ float g_als [NMAX * 4];
__device__ float g_ald [NMAX * 4];
__device__ int   g_cnt [NMAX];
__device__ int   g_off [NMAX + 1];
__device__ int   g_csr [EMAX];
__device__ __nv_bfloat16 g_ext [NMAX * 512];   // hi|lo bf16 GEMM input (stride 2*KIN)
__device__ __nv_bfloat16 g_wext[172032];       // W0:0..131071  W1:131072..163839  W2:163840..172031

#define WOFF0 0
#define WOFF1 131072
#define WOFF2 163840

static inline int cdiv(int a, int b) { return (a + b - 1) / b; }

__device__ __forceinline__ uint32_t pk(__nv_bfloat16 a, __nv_bfloat16 b) {
    return (uint32_t)__bfloat16_as_ushort(a) | ((uint32_t)__bfloat16_as_ushort(b) << 16);
}

// ------------------------------- CSR build ---------------------------------
__global__ void csr_count_k(const int* __restrict__ ei, int E, int Etot) {
    int i = blockIdx.x * blockDim.x + threadIdx.x;
    if (i >= Etot) return;
    int d = (i < E) ? ei[E + i] : (i - E);
    atomicAdd(&g_cnt[d], 1);
}
__global__ void csr_scan_k(int n, int Etot) {
    __shared__ int sh[32];
    __shared__ int carry;
    const int t = threadIdx.x, lane = t & 31, w = t >> 5;
    if (t == 0) carry = 0;
    __syncthreads();
    for (int base = 0; base < n; base += 1024) {
        int i = base + t;
        int v = (i < n) ? g_cnt[i] : 0;
        int x = v;
#pragma unroll
        for (int o = 1; o < 32; o <<= 1) {
            int y = __shfl_up_sync(0xffffffffu, x, o);
            if (lane >= o) x += y;
        }
        if (lane == 31) sh[w] = x;
        __syncthreads();
        if (w == 0) {
            int y = sh[lane];
#pragma unroll
            for (int o = 1; o < 32; o <<= 1) {
                int z = __shfl_up_sync(0xffffffffu, y, o);
                if (lane >= o) y += z;
            }
            sh[lane] = y;
        }
        __syncthreads();
        int incl = x + ((w == 0) ? 0 : sh[w - 1]);
        int excl = incl - v;
        if (i < n) { g_off[i] = carry + excl; g_cnt[i] = carry + excl; }
        __syncthreads();
        if (t == 1023) carry += incl;
        __syncthreads();
    }
    if (t == 0) g_off[n] = Etot;
}
__global__ void csr_fill_k(const int* __restrict__ ei, int E, int Etot) {
    int i = blockIdx.x * blockDim.x + threadIdx.x;
    if (i >= Etot) return;
    int s, d;
    if (i < E) { s = ei[i]; d = ei[E + i]; }
    else       { s = i - E; d = s; }
    int pos = atomicAdd(&g_cnt[d], 1);
    g_csr[pos] = s;
}

// ------------------- fused prep: x-ext, cnt zero, W-ext --------------------
__device__ __forceinline__ void wext_body(const float* __restrict__ W, int stride,
                                          int KIN, int idx, int outOff) {
    int nn   = idx & 63;
    int rest = idx >> 6;
    int kp   = rest % (KIN / 2);
    int t    = rest / (KIN / 2);
    int k0   = kp * 2;
    int col  = t * 64 + nn;
    float w0 = W[(size_t)k0 * stride + col];
    float w1 = W[(size_t)(k0 + 1) * stride + col];
    __nv_bfloat16 h0 = __float2bfloat16_rn(w0);
    __nv_bfloat16 h1 = __float2bfloat16_rn(w1);
    __nv_bfloat16 l0 = __float2bfloat16_rn(w0 - __bfloat162float(h0));
    __nv_bfloat16 l1 = __float2bfloat16_rn(w1 - __bfloat162float(h1));
    __nv_bfloat16* base = g_wext + outOff + ((size_t)t * 64 + nn) * (2 * KIN);
    *(uint32_t*)(base + k0)       = pk(h0, h1);
    *(uint32_t*)(base + KIN + k0) = pk(l0, l1);
}

__global__ void prep_k(const float* __restrict__ x, const float* __restrict__ W0,
                       const float* __restrict__ W1, const float* __restrict__ W2, int n) {
    int i = blockIdx.x * blockDim.x + threadIdx.x;
    const int extN = n * 64;                  // KIN=256 -> 64 float4 per row
    if (i < extN) {
        int row = i >> 6, q = i & 63;
        float4 v = ((const float4*)x)[i];
        __nv_bfloat16 h0 = __float2bfloat16_rn(v.x), h1 = __float2bfloat16_rn(v.y);
        __nv_bfloat16 h2 = __float2bfloat16_rn(v.z), h3 = __float2bfloat16_rn(v.w);
        __nv_bfloat16 l0 = __float2bfloat16_rn(v.x - __bfloat162float(h0));
        __nv_bfloat16 l1 = __float2bfloat16_rn(v.y - __bfloat162float(h1));
        __nv_bfloat16 l2 = __float2bfloat16_rn(v.z - __bfloat162float(h2));
        __nv_bfloat16 l3 = __float2bfloat16_rn(v.w - __bfloat162float(h3));
        __nv_bfloat16* d = g_ext + (size_t)row * 512 + 4 * q;
        *(uint2*)d         = make_uint2(pk(h0, h1), pk(h2, h3));
        *(uint2*)(d + 256) = make_uint2(pk(l0, l1), pk(l2, l3));
        return;
    }
    int j = i - extN;
    if (j < n) { g_cnt[j] = 0; return; }
    j -= n;
    if (j < 32768) { wext_body(W0, 256, 256, j, WOFF0); return; }
    j -= 32768;
    if (j < 8192)  { wext_body(W1, 64, 256, j, WOFF1); return; }
    j -= 8192;
    if (j < 2048)  { wext_body(W2, 64, 64, j, WOFF2); return; }
}

// --------------------- split-bf16 HMMA GEMM (128x64 tile) ------------------
// C[128,64] = A[128,KIN] @ W[KIN, tile*64 .. +64]; segments hi*hi+lo*hi+hi*lo.
// Epilogue also computes attention logits als/ald for this tile's head.
template<int KIN, int Hh>
__global__ void __launch_bounds__(256, 1)
gemm_mma_k(const float* __restrict__ a_s, const float* __restrict__ a_d,
           int nrows, int noutTot, int wOff) {
    constexpr int KEXT = 2 * KIN;
    constexpr int SA   = KEXT + 8;            // padded smem stride (elems)
    extern __shared__ __align__(16) __nv_bfloat16 sm[];
    __nv_bfloat16* As = sm;                   // [128][SA]
    __nv_bfloat16* Bs = sm + 128 * SA;        // [64][SA]
    const int tid = threadIdx.x, wid = tid >> 5, lane = tid & 31;
    const int r0 = blockIdx.x * 128;
    const int tl = blockIdx.y;

    constexpr int QA = KEXT / 8;              // uint4 per row
    for (int idx = tid; idx < 128 * QA; idx += 256) {
        int row = idx / QA, q = idx - row * QA;
        uint4 v = make_uint4(0u, 0u, 0u, 0u);
        if (r0 + row < nrows)
            v = ((const uint4*)(g_ext + (size_t)(r0 + row) * KEXT))[q];
        *(uint4*)(As + row * SA + q * 8) = v;
    }
    const __nv_bfloat16* Bg = g_wext + wOff + (size_t)tl * 64 * KEXT;
    for (int idx = tid; idx < 64 * QA; idx += 256) {
        int row = idx / QA, q = idx - row * QA;
        uint4 v = ((const uint4*)(Bg + (size_t)row * KEXT))[q];
        *(uint4*)(Bs + row * SA + q * 8) = v;
    }
    __syncthreads();

    const int g  = lane >> 2, tq = lane & 3;
    const int mr = wid * 16;
    float c[8][4];
#pragma unroll
    for (int j = 0; j < 8; j++)
#pragma unroll
        for (int i = 0; i < 4; i++) c[j][i] = 0.f;

    const __nv_bfloat16* Ar0 = As + (mr + g) * SA + tq * 2;
    const __nv_bfloat16* Ar1 = Ar0 + 8 * SA;
    const __nv_bfloat16* Br  = Bs + g * SA + tq * 2;

#pragma unroll
    for (int sg = 0; sg < 3; sg++) {
        const int ak0 = (sg == 1) ? KIN : 0;
        const int bk0 = (sg == 2) ? KIN : 0;
#pragma unroll 2
        for (int ks = 0; ks < KIN / 16; ks++) {
            const int ak = ak0 + ks * 16;
            const int bk = bk0 + ks * 16;
            uint32_t a0 = *(const uint32_t*)(Ar0 + ak);
            uint32_t a1 = *(const uint32_t*)(Ar1 + ak);
            uint32_t a2 = *(const uint32_t*)(Ar0 + ak + 8);
            uint32_t a3 = *(const uint32_t*)(Ar1 + ak + 8);
#pragma unroll
            for (int j = 0; j < 8; j++) {
                uint32_t b0 = *(const uint32_t*)(Br + j * 8 * SA + bk);
                uint32_t b1 = *(const uint32_t*)(Br + j * 8 * SA + bk + 8);
                asm volatile(
                    "mma.sync.aligned.m16n8k16.row.col.f32.bf16.bf16.f32 "
                    "{%0,%1,%2,%3}, {%4,%5,%6,%7}, {%8,%9}, {%0,%1,%2,%3};"
                    : "+f"(c[j][0]), "+f"(c[j][1]), "+f"(c[j][2]), "+f"(c[j][3])
                    : "r"(a0), "r"(a1), "r"(a2), "r"(a3), "r"(b0), "r"(b1));
            }
        }
    }

    const int gr0 = r0 + mr + g, gr1 = gr0 + 8;
    float* H0 = g_h + (size_t)gr0 * noutTot + tl * 64 + tq * 2;
    float* H1 = g_h + (size_t)gr1 * noutTot + tl * 64 + tq * 2;
    if (gr0 < nrows) {
#pragma unroll
        for (int j = 0; j < 8; j++) *(float2*)(H0 + j * 8) = make_float2(c[j][0], c[j][1]);
    }
    if (gr1 < nrows) {
#pragma unroll
        for (int j = 0; j < 8; j++) *(float2*)(H1 + j * 8) = make_float2(c[j][2], c[j][3]);
    }

    // fused attention logits: row dot a_s / a_d for head `tl`
    float s0 = 0.f, d0 = 0.f, s1 = 0.f, d1 = 0.f;
#pragma unroll
    for (int j = 0; j < 8; j++) {
        int cc = j * 8 + tq * 2;
        float av0 = __ldg(a_s + tl * 64 + cc), av1 = __ldg(a_s + tl * 64 + cc + 1);
        float bv0 = __ldg(a_d + tl * 64 + cc), bv1 = __ldg(a_d + tl * 64 + cc + 1);
        s0 += c[j][0] * av0 + c[j][1] * av1;
        d0 += c[j][0] * bv0 + c[j][1] * bv1;
        s1 += c[j][2] * av0 + c[j][3] * av1;
        d1 += c[j][2] * bv0 + c[j][3] * bv1;
    }
#pragma unroll
    for (int o = 1; o <= 2; o <<= 1) {
        s0 += __shfl_xor_sync(0xffffffffu, s0, o);
        d0 += __shfl_xor_sync(0xffffffffu, d0, o);
        s1 += __shfl_xor_sync(0xffffffffu, s1, o);
        d1 += __shfl_xor_sync(0xffffffffu, d1, o);
    }
    if (tq == 0) {
        if (gr0 < nrows) { g_als[gr0 * Hh + tl] = s0; g_ald[gr0 * Hh + tl] = d0; }
        if (gr1 < nrows) { g_als[gr1 * Hh + tl] = s1; g_ald[gr1 * Hh + tl] = d1; }
    }
}

// ------------- fused per-dst single-pass softmax aggregation ---------------
// One warp per dst; lane owns V = HOUT/32 contiguous channels.
// No max subtraction: logits are O(10), exp() safe in fp32; alpha identical.
// MODE 0: write hi|lo bf16 ext (input of next GEMM). MODE 1: write fp32 out.
template<int HOUT, int Hh, int MODE>
__global__ void aggr_k(const float* __restrict__ bias, float* __restrict__ outp, int n) {
    const int warp = (blockIdx.x * blockDim.x + threadIdx.x) >> 5;
    const int lane = threadIdx.x & 31;
    if (warp >= n) return;
    const int dst = warp;
    const int beg = g_off[dst], end = g_off[dst + 1];
    constexpr int V = HOUT / 32;

    float ald_own;
    if (Hh == 4) {
        float4 t = *(const float4*)(g_ald + dst * 4);
        ald_own = (lane & 2) ? ((lane & 1) ? t.w : t.z)
                             : ((lane & 1) ? t.y : t.x);
    } else ald_own = g_ald[dst];

    float acc[V];
#pragma unroll
    for (int k = 0; k < V; k++) acc[k] = 0.f;
    float den = 0.f;
    const int headL = (Hh == 1) ? 0 : (lane >> 3);

    int sNext = g_csr[beg];                  // every dst has >=1 edge (self loop)
    for (int e = beg; e < end; e++) {
        int s = sNext;
        if (e + 1 < end) sNext = g_csr[e + 1];
        float exh = 0.f;
        if (lane < Hh) {
            float v = g_als[s * Hh + lane] + ald_own;
            v = v > 0.f ? v : 0.2f * v;
            exh = __expf(v);
            den += exh;
        }
        float ex = __shfl_sync(0xffffffffu, exh, headL);
        if (V == 8) {
            const float4* hs = (const float4*)(g_h + (size_t)s * HOUT);
            float4 p0 = hs[lane * 2], p1 = hs[lane * 2 + 1];
            acc[0] += ex * p0.x; acc[1] += ex * p0.y;
            acc[2] += ex * p0.z; acc[3] += ex * p0.w;
            acc[4] += ex * p1.x; acc[5] += ex * p1.y;
            acc[6] += ex * p1.z; acc[7] += ex * p1.w;
        } else {
            const float2* hs = (const float2*)(g_h + (size_t)s * HOUT);
            float2 p = hs[lane];
            acc[0] += ex * p.x; acc[1] += ex * p.y;
        }
    }

    float dv  = __shfl_sync(0xffffffffu, den, headL);
    float inv = 1.f / (dv + 1e-16f);
    float r[V];
    if (V == 8) {
        float4 b0 = *(const float4*)(bias + lane * 8);
        float4 b1 = *(const float4*)(bias + lane * 8 + 4);
        r[0] = acc[0] * inv + b0.x; r[1] = acc[1] * inv + b0.y;
        r[2] = acc[2] * inv + b0.z; r[3] = acc[3] * inv + b0.w;
        r[4] = acc[4] * inv + b1.x; r[5] = acc[5] * inv + b1.y;
        r[6] = acc[6] * inv + b1.z; r[7] = acc[7] * inv + b1.w;
    } else {
        float2 b = *(const float2*)(bias + lane * 2);
        r[0] = acc[0] * inv + b.x; r[1] = acc[1] * inv + b.y;
    }
#pragma unroll
    for (int j = 0; j < V; j++) r[j] = r[j] > 0.f ? r[j] : expm1f(r[j]);

    if (MODE == 1) {
        if (V == 2)
            *(float2*)(outp + (size_t)dst * HOUT + lane * 2) = make_float2(r[0], r[1]);
    } else {
        __nv_bfloat16 hi[V], lo[V];
#pragma unroll
        for (int j = 0; j < V; j++) {
            hi[j] = __float2bfloat16_rn(r[j]);
            lo[j] = __float2bfloat16_rn(r[j] - __bfloat162float(hi[j]));
        }
        if (V == 8) {
            __nv_bfloat16* eb = g_ext + (size_t)dst * 512 + lane * 8;
            *(uint4*)eb         = make_uint4(pk(hi[0], hi[1]), pk(hi[2], hi[3]),
                                             pk(hi[4], hi[5]), pk(hi[6], hi[7]));
            *(uint4*)(eb + 256) = make_uint4(pk(lo[0], lo[1]), pk(lo[2], lo[3]),
                                             pk(lo[4], lo[5]), pk(lo[6], lo[7]));
        } else {
            __nv_bfloat16* eb = g_ext + (size_t)dst * 128 + lane * 2;
            *(uint32_t*)eb        = pk(hi[0], hi[1]);
            *(uint32_t*)(eb + 64) = pk(lo[0], lo[1]);
        }
    }
}

// ---------------------------------------------------------------------------
extern "C" void kernel_launch(void* const* d_in, const int* in_sizes, int n_in,
                              void* d_out, int out_size) {
    const float* x   = (const float*)d_in[0];
    const int*   ei  = (const int*)  d_in[1];
    const float* W0  = (const float*)d_in[2];
    const float* as0 = (const float*)d_in[3];
    const float* ad0 = (const float*)d_in[4];
    const float* b0  = (const float*)d_in[5];
    const float* W1  = (const float*)d_in[6];
    const float* as1 = (const float*)d_in[7];
    const float* ad1 = (const float*)d_in[8];
    const float* b1  = (const float*)d_in[9];
    const float* W2  = (const float*)d_in[10];
    const float* as2 = (const float*)d_in[11];
    const float* ad2 = (const float*)d_in[12];
    const float* b2  = (const float*)d_in[13];
    float* out = (float*)d_out;

    const int n    = in_sizes[0] / INCH;   // 50000
    const int E    = in_sizes[1] / 2;      // 800000
    const int Etot = E + n;

    const int SM256 = (128 + 64) * (512 + 8) * 2;   // 199,680 B
    const int SM64  = (128 + 64) * (128 + 8) * 2;   //  52,224 B
    cudaFuncSetAttribute((const void*)gemm_mma_k<256, 4>, cudaFuncAttributeMaxDynamicSharedMemorySize, SM256);
    cudaFuncSetAttribute((const void*)gemm_mma_k<256, 1>, cudaFuncAttributeMaxDynamicSharedMemorySize, SM256);
    cudaFuncSetAttribute((const void*)gemm_mma_k<64, 1>,  cudaFuncAttributeMaxDynamicSharedMemorySize, SM64);

    // ---- prep (x ext + cnt zero + all W ext) and CSR build ----
    const int prepTot = n * 64 + n + 32768 + 8192 + 2048;
    prep_k<<<cdiv(prepTot, 256), 256>>>(x, W0, W1, W2, n);
    csr_count_k<<<cdiv(Etot, 256), 256>>>(ei, E, Etot);
    csr_scan_k <<<1, 1024>>>(n, Etot);
    csr_fill_k <<<cdiv(Etot, 256), 256>>>(ei, E, Etot);

    const int nb = cdiv(n, 128);

    // ---- Layer 0: 256 -> 4x64 concat ----
    gemm_mma_k<256, 4><<<dim3(nb, 4), 256, SM256>>>(as0, ad0, n, 256, WOFF0);
    aggr_k<256, 4, 0><<<cdiv(n * 32, 256), 256>>>(b0, out, n);

    // ---- Layer 1: 256 -> 64 ----
    gemm_mma_k<256, 1><<<dim3(nb, 1), 256, SM256>>>(as1, ad1, n, 64, WOFF1);
    aggr_k<64, 1, 0><<<cdiv(n * 32, 256), 256>>>(b1, out, n);

    // ---- Layer 2: 64 -> 64 ----
    gemm_mma_k<64, 1><<<dim3(nb, 1), 256, SM64>>>(as2, ad2, n, 64, WOFF2);
    aggr_k<64, 1, 1><<<cdiv(n * 32, 256), 256>>>(b2, out, n);
}

// round 8
// speedup vs baseline: 3.4984x; 1.1885x over previous
#include <cuda_runtime.h>
#include <cuda_bf16.h>
#include <cuda_fp16.h>
#include <math_constants.h>
#include <cstdint>

// ---------------------------------------------------------------------------
// ModifiedGAT: 3-layer GAT (PyG GATConv, add_self_loops=True)
//   L0: 256 -> 4x64 concat=256, ELU;  L1: 256 -> 64, ELU;  L2: 64 -> 64, ELU
// CSR-gather single-pass-softmax aggregation (fp16 h) + split-bf16 HMMA GEMMs
// (ldmatrix fragments) with fused attention-logit epilogue.
// ---------------------------------------------------------------------------

#define NMAX   50000
#define EMAX   850000
#define INCH   256
#define OUTC   64

__device__ float g_h   [NMAX * 128];           // GEMM output, stored as __half (256 ch max)
__device__ float g_als [NMAX * 4];
__device__ float g_ald [NMAX * 4];
__device__ int   g_cnt [NMAX];                 // statically 0; re-zeroed by last aggr
__device__ int   g_off [NMAX + 1];
__device__ int   g_csr [EMAX];
__device__ int   g_bsum [64];
__device__ int   g_bsumx[64];
__device__ __nv_bfloat16 g_ext [NMAX * 512];   // hi|lo bf16 GEMM input (stride 2*KIN)
__device__ __nv_bfloat16 g_wext[172032];       // W0 | W1 | W2 (hi|lo, [n][kext])

#define WOFF0 0
#define WOFF1 131072
#define WOFF2 163840

static inline int cdiv(int a, int b) { return (a + b - 1) / b; }

__device__ __forceinline__ uint32_t pk(__nv_bfloat16 a, __nv_bfloat16 b) {
    return (uint32_t)__bfloat16_as_ushort(a) | ((uint32_t)__bfloat16_as_ushort(b) << 16);
}
__device__ __forceinline__ void ldsm_x4(uint32_t& r0, uint32_t& r1, uint32_t& r2,
                                        uint32_t& r3, uint32_t addr) {
    asm volatile("ldmatrix.sync.aligned.m8n8.x4.shared.b16 {%0,%1,%2,%3}, [%4];"
                 : "=r"(r0), "=r"(r1), "=r"(r2), "=r"(r3) : "r"(addr));
}
__device__ __forceinline__ void ldsm_x2(uint32_t& r0, uint32_t& r1, uint32_t addr) {
    asm volatile("ldmatrix.sync.aligned.m8n8.x2.shared.b16 {%0,%1}, [%2];"
                 : "=r"(r0), "=r"(r1) : "r"(addr));
}

// ------------------- fused prep: edge count, x-ext, W-ext ------------------
__device__ __forceinline__ void wext_body(const float* __restrict__ W, int stride,
                                          int KIN, int idx, int outOff) {
    int nn   = idx & 63;
    int rest = idx >> 6;
    int kp   = rest % (KIN / 2);
    int t    = rest / (KIN / 2);
    int k0   = kp * 2;
    int col  = t * 64 + nn;
    float w0 = W[(size_t)k0 * stride + col];
    float w1 = W[(size_t)(k0 + 1) * stride + col];
    __nv_bfloat16 h0 = __float2bfloat16_rn(w0);
    __nv_bfloat16 h1 = __float2bfloat16_rn(w1);
    __nv_bfloat16 l0 = __float2bfloat16_rn(w0 - __bfloat162float(h0));
    __nv_bfloat16 l1 = __float2bfloat16_rn(w1 - __bfloat162float(h1));
    __nv_bfloat16* base = g_wext + outOff + ((size_t)t * 64 + nn) * (2 * KIN);
    *(uint32_t*)(base + k0)       = pk(h0, h1);
    *(uint32_t*)(base + KIN + k0) = pk(l0, l1);
}

__global__ void prep_k(const float* __restrict__ x, const int* __restrict__ ei,
                       const float* __restrict__ W0, const float* __restrict__ W1,
                       const float* __restrict__ W2, int n, int E, int Etot) {
    int i = blockIdx.x * blockDim.x + threadIdx.x;
    if (i < Etot) {                            // CSR degree count (g_cnt starts 0)
        int d = (i < E) ? ei[E + i] : (i - E);
        atomicAdd(&g_cnt[d], 1);
        return;
    }
    int j = i - Etot;
    const int extN = n * 64;                   // KIN=256 -> 64 float4 per row
    if (j < extN) {
        int row = j >> 6, q = j & 63;
        float4 v = ((const float4*)x)[j];
        __nv_bfloat16 h0 = __float2bfloat16_rn(v.x), h1 = __float2bfloat16_rn(v.y);
        __nv_bfloat16 h2 = __float2bfloat16_rn(v.z), h3 = __float2bfloat16_rn(v.w);
        __nv_bfloat16 l0 = __float2bfloat16_rn(v.x - __bfloat162float(h0));
        __nv_bfloat16 l1 = __float2bfloat16_rn(v.y - __bfloat162float(h1));
        __nv_bfloat16 l2 = __float2bfloat16_rn(v.z - __bfloat162float(h2));
        __nv_bfloat16 l3 = __float2bfloat16_rn(v.w - __bfloat162float(h3));
        __nv_bfloat16* d = g_ext + (size_t)row * 512 + 4 * q;
        *(uint2*)d         = make_uint2(pk(h0, h1), pk(h2, h3));
        *(uint2*)(d + 256) = make_uint2(pk(l0, l1), pk(l2, l3));
        return;
    }
    j -= extN;
    if (j < 32768) { wext_body(W0, 256, 256, j, WOFF0); return; }
    j -= 32768;
    if (j < 8192)  { wext_body(W1, 64, 256, j, WOFF1); return; }
    j -= 8192;
    if (j < 2048)  { wext_body(W2, 64, 64, j, WOFF2); return; }
}

// --------------------------- parallel CSR scan -----------------------------
__global__ void scan1_k(int n) {               // per-1024-block local exclusive scan
    __shared__ int sh[32];
    const int t = threadIdx.x, lane = t & 31, w = t >> 5;
    int i = blockIdx.x * 1024 + t;
    int v = (i < n) ? g_cnt[i] : 0;
    int x = v;
#pragma unroll
    for (int o = 1; o < 32; o <<= 1) {
        int y = __shfl_up_sync(0xffffffffu, x, o);
        if (lane >= o) x += y;
    }
    if (lane == 31) sh[w] = x;
    __syncthreads();
    if (w == 0) {
        int y = sh[lane];
#pragma unroll
        for (int o = 1; o < 32; o <<= 1) {
            int z = __shfl_up_sync(0xffffffffu, y, o);
            if (lane >= o) y += z;
        }
        sh[lane] = y;
    }
    __syncthreads();
    int incl = x + ((w == 0) ? 0 : sh[w - 1]);
    if (i < n) g_off[i] = incl - v;
    if (t == 1023) g_bsum[blockIdx.x] = incl;
}
__global__ void scan2_k(int nb, int n, int Etot) {  // scan of block sums
    __shared__ int sh[32];
    const int t = threadIdx.x, lane = t & 31, w = t >> 5;
    int v = (t < nb) ? g_bsum[t] : 0;
    int x = v;
#pragma unroll
    for (int o = 1; o < 32; o <<= 1) {
        int y = __shfl_up_sync(0xffffffffu, x, o);
        if (lane >= o) x += y;
    }
    if (lane == 31) sh[w] = x;
    __syncthreads();
    if (w == 0) {
        int y = sh[lane];
#pragma unroll
        for (int o = 1; o < 32; o <<= 1) {
            int z = __shfl_up_sync(0xffffffffu, y, o);
            if (lane >= o) y += z;
        }
        sh[lane] = y;
    }
    __syncthreads();
    int incl = x + ((w == 0) ? 0 : sh[w - 1]);
    if (t < nb) g_bsumx[t] = incl - v;
    if (t == 0) g_off[n] = Etot;
}
__global__ void scan3_k(int n) {               // add block base; init fill cursors
    int i = blockIdx.x * blockDim.x + threadIdx.x;
    if (i < n) {
        int o = g_off[i] + g_bsumx[i >> 10];
        g_off[i] = o;
        g_cnt[i] = o;
    }
}
__global__ void csr_fill_k(const int* __restrict__ ei, int E, int Etot) {
    int i = blockIdx.x * blockDim.x + threadIdx.x;
    if (i >= Etot) return;
    int s, d;
    if (i < E) { s = ei[i]; d = ei[E + i]; }
    else       { s = i - E; d = s; }
    int pos = atomicAdd(&g_cnt[d], 1);
    g_csr[pos] = s;
}

// --------------------- split-bf16 HMMA GEMM (128x64 tile) ------------------
// C[128,64] = A[128,KIN] @ W[KIN, tile*64 .. +64]; segments hi*hi+lo*hi+hi*lo.
// Output stored fp16; epilogue computes attention logits for this tile's head.
template<int KIN, int Hh>
__global__ void __launch_bounds__(256, 1)
gemm_mma_k(const float* __restrict__ a_s, const float* __restrict__ a_d,
           int nrows, int noutTot, int wOff) {
    constexpr int KEXT = 2 * KIN;
    constexpr int SA   = KEXT + 8;            // padded smem stride (elems)
    extern __shared__ __align__(16) __nv_bfloat16 sm[];
    __nv_bfloat16* As = sm;                   // [128][SA]
    __nv_bfloat16* Bs = sm + 128 * SA;        // [64][SA]
    const int tid = threadIdx.x, wid = tid >> 5, lane = tid & 31;
    const int r0 = blockIdx.x * 128;
    const int tl = blockIdx.y;

    constexpr int QA = KEXT / 8;              // uint4 per row
    for (int idx = tid; idx < 128 * QA; idx += 256) {
        int row = idx / QA, q = idx - row * QA;
        uint4 v = make_uint4(0u, 0u, 0u, 0u);
        if (r0 + row < nrows)
            v = ((const uint4*)(g_ext + (size_t)(r0 + row) * KEXT))[q];
        *(uint4*)(As + row * SA + q * 8) = v;
    }
    const __nv_bfloat16* Bg = g_wext + wOff + (size_t)tl * 64 * KEXT;
    for (int idx = tid; idx < 64 * QA; idx += 256) {
        int row = idx / QA, q = idx - row * QA;
        uint4 v = ((const uint4*)(Bg + (size_t)row * KEXT))[q];
        *(uint4*)(Bs + row * SA + q * 8) = v;
    }
    __syncthreads();

    const int g  = lane >> 2, tq = lane & 3;
    const int mr = wid * 16;
    float c[8][4];
#pragma unroll
    for (int j = 0; j < 8; j++)
#pragma unroll
        for (int i = 0; i < 4; i++) c[j][i] = 0.f;

    // ldmatrix base addresses
    const int mi = lane >> 3;
    const uint32_t baseA = (uint32_t)__cvta_generic_to_shared(As)
        + ((mr + (lane & 7) + (mi & 1) * 8) * SA + (mi >> 1) * 8) * 2;
    uint32_t baseB[8];
#pragma unroll
    for (int j = 0; j < 8; j++)
        baseB[j] = (uint32_t)__cvta_generic_to_shared(Bs)
            + ((j * 8 + (lane & 7)) * SA + ((lane >> 3) & 1) * 8) * 2;

#pragma unroll
    for (int sg = 0; sg < 3; sg++) {
        const int ak0 = (sg == 1) ? KIN : 0;
        const int bk0 = (sg == 2) ? KIN : 0;
#pragma unroll 2
        for (int ks = 0; ks < KIN / 16; ks++) {
            uint32_t a0, a1, a2, a3;
            ldsm_x4(a0, a1, a2, a3, baseA + (ak0 + ks * 16) * 2);
#pragma unroll
            for (int j = 0; j < 8; j++) {
                uint32_t b0, b1;
                ldsm_x2(b0, b1, baseB[j] + (bk0 + ks * 16) * 2);
                asm volatile(
                    "mma.sync.aligned.m16n8k16.row.col.f32.bf16.bf16.f32 "
                    "{%0,%1,%2,%3}, {%4,%5,%6,%7}, {%8,%9}, {%0,%1,%2,%3};"
                    : "+f"(c[j][0]), "+f"(c[j][1]), "+f"(c[j][2]), "+f"(c[j][3])
                    : "r"(a0), "r"(a1), "r"(a2), "r"(a3), "r"(b0), "r"(b1));
            }
        }
    }

    // store fp16
    __half* g_h16 = (__half*)g_h;
    const int gr0 = r0 + mr + g, gr1 = gr0 + 8;
    if (gr0 < nrows) {
        __half* H0 = g_h16 + (size_t)gr0 * noutTot + tl * 64 + tq * 2;
#pragma unroll
        for (int j = 0; j < 8; j++)
            *(__half2*)(H0 + j * 8) = __floats2half2_rn(c[j][0], c[j][1]);
    }
    if (gr1 < nrows) {
        __half* H1 = g_h16 + (size_t)gr1 * noutTot + tl * 64 + tq * 2;
#pragma unroll
        for (int j = 0; j < 8; j++)
            *(__half2*)(H1 + j * 8) = __floats2half2_rn(c[j][2], c[j][3]);
    }

    // fused attention logits: row dot a_s / a_d for head `tl` (fp32 regs)
    float s0 = 0.f, d0 = 0.f, s1 = 0.f, d1 = 0.f;
#pragma unroll
    for (int j = 0; j < 8; j++) {
        int cc = j * 8 + tq * 2;
        float av0 = __ldg(a_s + tl * 64 + cc), av1 = __ldg(a_s + tl * 64 + cc + 1);
        float bv0 = __ldg(a_d + tl * 64 + cc), bv1 = __ldg(a_d + tl * 64 + cc + 1);
        s0 += c[j][0] * av0 + c[j][1] * av1;
        d0 += c[j][0] * bv0 + c[j][1] * bv1;
        s1 += c[j][2] * av0 + c[j][3] * av1;
        d1 += c[j][2] * bv0 + c[j][3] * bv1;
    }
#pragma unroll
    for (int o = 1; o <= 2; o <<= 1) {
        s0 += __shfl_xor_sync(0xffffffffu, s0, o);
        d0 += __shfl_xor_sync(0xffffffffu, d0, o);
        s1 += __shfl_xor_sync(0xffffffffu, s1, o);
        d1 += __shfl_xor_sync(0xffffffffu, d1, o);
    }
    if (tq == 0) {
        if (gr0 < nrows) { g_als[gr0 * Hh + tl] = s0; g_ald[gr0 * Hh + tl] = d0; }
        if (gr1 < nrows) { g_als[gr1 * Hh + tl] = s1; g_ald[gr1 * Hh + tl] = d1; }
    }
}

// ------------- fused per-dst single-pass softmax aggregation ---------------
// One warp per dst; lane owns V = HOUT/32 contiguous channels. h is fp16.
// No max subtraction: logits are O(10), exp() safe in fp32; alpha identical.
// MODE 0: write hi|lo bf16 ext (next GEMM input). MODE 1: fp32 out + g_cnt=0.
template<int HOUT, int Hh, int MODE>
__global__ void aggr_k(const float* __restrict__ bias, float* __restrict__ outp, int n) {
    const int warp = (blockIdx.x * blockDim.x + threadIdx.x) >> 5;
    const int lane = threadIdx.x & 31;
    if (warp >= n) return;
    const int dst = warp;
    const int beg = g_off[dst], end = g_off[dst + 1];
    constexpr int V = HOUT / 32;
    const __half* g_h16 = (const __half*)g_h;

    float ald_own;
    if (Hh == 4) {
        float4 t = *(const float4*)(g_ald + dst * 4);
        ald_own = (lane & 2) ? ((lane & 1) ? t.w : t.z)
                             : ((lane & 1) ? t.y : t.x);
    } else ald_own = g_ald[dst];

    float acc[V];
#pragma unroll
    for (int k = 0; k < V; k++) acc[k] = 0.f;
    float den = 0.f;
    const int headL = (Hh == 1) ? 0 : (lane >> 3);

    int sNext = g_csr[beg];                  // every dst has >=1 edge (self loop)
    for (int e = beg; e < end; e++) {
        int s = sNext;
        if (e + 1 < end) sNext = g_csr[e + 1];
        float exh = 0.f;
        if (lane < Hh) {
            float v = g_als[s * Hh + lane] + ald_own;
            v = v > 0.f ? v : 0.2f * v;
            exh = __expf(v);
            den += exh;
        }
        float ex = __shfl_sync(0xffffffffu, exh, headL);
        if (V == 8) {
            uint4 p = ((const uint4*)(g_h16 + (size_t)s * HOUT))[lane];
            float2 f0 = __half22float2(*(__half2*)&p.x);
            float2 f1 = __half22float2(*(__half2*)&p.y);
            float2 f2 = __half22float2(*(__half2*)&p.z);
            float2 f3 = __half22float2(*(__half2*)&p.w);
            acc[0] += ex * f0.x; acc[1] += ex * f0.y;
            acc[2] += ex * f1.x; acc[3] += ex * f1.y;
            acc[4] += ex * f2.x; acc[5] += ex * f2.y;
            acc[6] += ex * f3.x; acc[7] += ex * f3.y;
        } else {
            uint32_t p = ((const uint32_t*)(g_h16 + (size_t)s * HOUT))[lane];
            float2 f = __half22float2(*(__half2*)&p);
            acc[0] += ex * f.x; acc[1] += ex * f.y;
        }
    }

    float dv  = __shfl_sync(0xffffffffu, den, headL);
    float inv = 1.f / (dv + 1e-16f);
    float r[V];
    if (V == 8) {
        float4 b0 = *(const float4*)(bias + lane * 8);
        float4 b1 = *(const float4*)(bias + lane * 8 + 4);
        r[0] = acc[0] * inv + b0.x; r[1] = acc[1] * inv + b0.y;
        r[2] = acc[2] * inv + b0.z; r[3] = acc[3] * inv + b0.w;
        r[4] = acc[4] * inv + b1.x; r[5] = acc[5] * inv + b1.y;
        r[6] = acc[6] * inv + b1.z; r[7] = acc[7] * inv + b1.w;
    } else {
        float2 b = *(const float2*)(bias + lane * 2);
        r[0] = acc[0] * inv + b.x; r[1] = acc[1] * inv + b.y;
    }
#pragma unroll
    for (int j = 0; j < V; j++) r[j] = r[j] > 0.f ? r[j] : expm1f(r[j]);

    if (MODE == 1) {
        if (V == 2)
            *(float2*)(outp + (size_t)dst * HOUT + lane * 2) = make_float2(r[0], r[1]);
        if (lane == 0) g_cnt[dst] = 0;       // reset cursors for next replay
    } else {
        __nv_bfloat16 hi[V], lo[V];
#pragma unroll
        for (int j = 0; j < V; j++) {
            hi[j] = __float2bfloat16_rn(r[j]);
            lo[j] = __float2bfloat16_rn(r[j] - __bfloat162float(hi[j]));
        }
        if (V == 8) {
            __nv_bfloat16* eb = g_ext + (size_t)dst * 512 + lane * 8;
            *(uint4*)eb         = make_uint4(pk(hi[0], hi[1]), pk(hi[2], hi[3]),
                                             pk(hi[4], hi[5]), pk(hi[6], hi[7]));
            *(uint4*)(eb + 256) = make_uint4(pk(lo[0], lo[1]), pk(lo[2], lo[3]),
                                             pk(lo[4], lo[5]), pk(lo[6], lo[7]));
        } else {
            __nv_bfloat16* eb = g_ext + (size_t)dst * 128 + lane * 2;
            *(uint32_t*)eb        = pk(hi[0], hi[1]);
            *(uint32_t*)(eb + 64) = pk(lo[0], lo[1]);
        }
    }
}

// ---------------------------------------------------------------------------
extern "C" void kernel_launch(void* const* d_in, const int* in_sizes, int n_in,
                              void* d_out, int out_size) {
    const float* x   = (const float*)d_in[0];
    const int*   ei  = (const int*)  d_in[1];
    const float* W0  = (const float*)d_in[2];
    const float* as0 = (const float*)d_in[3];
    const float* ad0 = (const float*)d_in[4];
    const float* b0  = (const float*)d_in[5];
    const float* W1  = (const float*)d_in[6];
    const float* as1 = (const float*)d_in[7];
    const float* ad1 = (const float*)d_in[8];
    const float* b1  = (const float*)d_in[9];
    const float* W2  = (const float*)d_in[10];
    const float* as2 = (const float*)d_in[11];
    const float* ad2 = (const float*)d_in[12];
    const float* b2  = (const float*)d_in[13];
    float* out = (float*)d_out;

    const int n    = in_sizes[0] / INCH;   // 50000
    const int E    = in_sizes[1] / 2;      // 800000
    const int Etot = E + n;

    const int SM256 = (128 + 64) * (512 + 8) * 2;   // 199,680 B
    const int SM64  = (128 + 64) * (128 + 8) * 2;   //  52,224 B
    cudaFuncSetAttribute((const void*)gemm_mma_k<256, 4>, cudaFuncAttributeMaxDynamicSharedMemorySize, SM256);
    cudaFuncSetAttribute((const void*)gemm_mma_k<256, 1>, cudaFuncAttributeMaxDynamicSharedMemorySize, SM256);
    cudaFuncSetAttribute((const void*)gemm_mma_k<64, 1>,  cudaFuncAttributeMaxDynamicSharedMemorySize, SM64);

    // ---- prep (count + x ext + W ext), parallel scan, fill ----
    const int prepTot = Etot + n * 64 + 32768 + 8192 + 2048;
    prep_k<<<cdiv(prepTot, 256), 256>>>(x, ei, W0, W1, W2, n, E, Etot);
    const int nb1 = cdiv(n, 1024);
    scan1_k<<<nb1, 1024>>>(n);
    scan2_k<<<1, 1024>>>(nb1, n, Etot);
    scan3_k<<<cdiv(n, 256), 256>>>(n);
    csr_fill_k<<<cdiv(Etot, 256), 256>>>(ei, E, Etot);

    const int nb = cdiv(n, 128);

    // ---- Layer 0: 256 -> 4x64 concat ----
    gemm_mma_k<256, 4><<<dim3(nb, 4), 256, SM256>>>(as0, ad0, n, 256, WOFF0);
    aggr_k<256, 4, 0><<<cdiv(n * 32, 256), 256>>>(b0, out, n);

    // ---- Layer 1: 256 -> 64 ----
    gemm_mma_k<256, 1><<<dim3(nb, 1), 256, SM256>>>(as1, ad1, n, 64, WOFF1);
    aggr_k<64, 1, 0><<<cdiv(n * 32, 256), 256>>>(b1, out, n);

    // ---- Layer 2: 64 -> 64 ----
    gemm_mma_k<64, 1><<<dim3(nb, 1), 256, SM64>>>(as2, ad2, n, 64, WOFF2);
    aggr_k<64, 1, 1><<<cdiv(n * 32, 256), 256>>>(b2, out, n);
}

// round 12
// speedup vs baseline: 3.7670x; 1.0768x over previous
#include <cuda_runtime.h>
#include <cuda_bf16.h>
#include <cuda_fp16.h>
#include <math_constants.h>
#include <cstdint>

// ---------------------------------------------------------------------------
// ModifiedGAT: 3-layer GAT (PyG GATConv, add_self_loops=True)
//   L0: 256 -> 4x64 concat=256, ELU;  L1: 256 -> 64, ELU;  L2: 64 -> 64, ELU
// CSR-gather single-pass-softmax aggregation (fp16 h, MLP-4 unrolled) +
// split-bf16 HMMA GEMMs (ldmatrix) with fused attention-logit epilogue.
// ---------------------------------------------------------------------------

#define NMAX   50000
#define EMAX   850000
#define INCH   256
#define OUTC   64

__device__ float g_h   [NMAX * 128];           // GEMM output, stored as __half (256 ch max)
__device__ float g_als [NMAX * 4];
__device__ float g_ald [NMAX * 4];
__device__ int   g_cnt [NMAX];                 // statically 0; re-zeroed by last aggr
__device__ int   g_off [NMAX + 1];
__device__ int   g_csr [EMAX];
__device__ int   g_bsum [64];
__device__ int   g_bsumx[64];
__device__ __nv_bfloat16 g_ext [NMAX * 512];   // hi|lo bf16 GEMM input (stride 2*KIN)
__device__ __nv_bfloat16 g_wext[172032];       // W0 | W1 | W2 (hi|lo, [n][kext])

#define WOFF0 0
#define WOFF1 131072
#define WOFF2 163840

static inline int cdiv(int a, int b) { return (a + b - 1) / b; }

__device__ __forceinline__ uint32_t pk(__nv_bfloat16 a, __nv_bfloat16 b) {
    return (uint32_t)__bfloat16_as_ushort(a) | ((uint32_t)__bfloat16_as_ushort(b) << 16);
}
__device__ __forceinline__ void ldsm_x4(uint32_t& r0, uint32_t& r1, uint32_t& r2,
                                        uint32_t& r3, uint32_t addr) {
    asm volatile("ldmatrix.sync.aligned.m8n8.x4.shared.b16 {%0,%1,%2,%3}, [%4];"
                 : "=r"(r0), "=r"(r1), "=r"(r2), "=r"(r3) : "r"(addr));
}
__device__ __forceinline__ void ldsm_x2(uint32_t& r0, uint32_t& r1, uint32_t addr) {
    asm volatile("ldmatrix.sync.aligned.m8n8.x2.shared.b16 {%0,%1}, [%2];"
                 : "=r"(r0), "=r"(r1) : "r"(addr));
}

// ------------------- fused prep: edge count, x-ext, W-ext ------------------
__device__ __forceinline__ void wext_body(const float* __restrict__ W, int stride,
                                          int KIN, int idx, int outOff) {
    int nn   = idx & 63;
    int rest = idx >> 6;
    int kp   = rest % (KIN / 2);
    int t    = rest / (KIN / 2);
    int k0   = kp * 2;
    int col  = t * 64 + nn;
    float w0 = W[(size_t)k0 * stride + col];
    float w1 = W[(size_t)(k0 + 1) * stride + col];
    __nv_bfloat16 h0 = __float2bfloat16_rn(w0);
    __nv_bfloat16 h1 = __float2bfloat16_rn(w1);
    __nv_bfloat16 l0 = __float2bfloat16_rn(w0 - __bfloat162float(h0));
    __nv_bfloat16 l1 = __float2bfloat16_rn(w1 - __bfloat162float(h1));
    __nv_bfloat16* base = g_wext + outOff + ((size_t)t * 64 + nn) * (2 * KIN);
    *(uint32_t*)(base + k0)       = pk(h0, h1);
    *(uint32_t*)(base + KIN + k0) = pk(l0, l1);
}

__global__ void prep_k(const float* __restrict__ x, const int* __restrict__ ei,
                       const float* __restrict__ W0, const float* __restrict__ W1,
                       const float* __restrict__ W2, int n, int E, int Etot) {
    int i = blockIdx.x * blockDim.x + threadIdx.x;
    if (i < Etot) {                            // CSR degree count (g_cnt starts 0)
        int d = (i < E) ? ei[E + i] : (i - E);
        atomicAdd(&g_cnt[d], 1);
        return;
    }
    int j = i - Etot;
    const int extN = n * 64;                   // KIN=256 -> 64 float4 per row
    if (j < extN) {
        int row = j >> 6, q = j & 63;
        float4 v = ((const float4*)x)[j];
        __nv_bfloat16 h0 = __float2bfloat16_rn(v.x), h1 = __float2bfloat16_rn(v.y);
        __nv_bfloat16 h2 = __float2bfloat16_rn(v.z), h3 = __float2bfloat16_rn(v.w);
        __nv_bfloat16 l0 = __float2bfloat16_rn(v.x - __bfloat162float(h0));
        __nv_bfloat16 l1 = __float2bfloat16_rn(v.y - __bfloat162float(h1));
        __nv_bfloat16 l2 = __float2bfloat16_rn(v.z - __bfloat162float(h2));
        __nv_bfloat16 l3 = __float2bfloat16_rn(v.w - __bfloat162float(h3));
        __nv_bfloat16* d = g_ext + (size_t)row * 512 + 4 * q;
        *(uint2*)d         = make_uint2(pk(h0, h1), pk(h2, h3));
        *(uint2*)(d + 256) = make_uint2(pk(l0, l1), pk(l2, l3));
        return;
    }
    j -= extN;
    if (j < 32768) { wext_body(W0, 256, 256, j, WOFF0); return; }
    j -= 32768;
    if (j < 8192)  { wext_body(W1, 64, 256, j, WOFF1); return; }
    j -= 8192;
    if (j < 2048)  { wext_body(W2, 64, 64, j, WOFF2); return; }
}

// --------------------------- parallel CSR scan -----------------------------
__global__ void scan1_k(int n) {               // per-1024-block local exclusive scan
    __shared__ int sh[32];
    const int t = threadIdx.x, lane = t & 31, w = t >> 5;
    int i = blockIdx.x * 1024 + t;
    int v = (i < n) ? g_cnt[i] : 0;
    int x = v;
#pragma unroll
    for (int o = 1; o < 32; o <<= 1) {
        int y = __shfl_up_sync(0xffffffffu, x, o);
        if (lane >= o) x += y;
    }
    if (lane == 31) sh[w] = x;
    __syncthreads();
    if (w == 0) {
        int y = sh[lane];
#pragma unroll
        for (int o = 1; o < 32; o <<= 1) {
            int z = __shfl_up_sync(0xffffffffu, y, o);
            if (lane >= o) y += z;
        }
        sh[lane] = y;
    }
    __syncthreads();
    int incl = x + ((w == 0) ? 0 : sh[w - 1]);
    if (i < n) g_off[i] = incl - v;
    if (t == 1023) g_bsum[blockIdx.x] = incl;
}
__global__ void scan2_k(int nb, int n, int Etot) {  // scan of block sums
    __shared__ int sh[32];
    const int t = threadIdx.x, lane = t & 31, w = t >> 5;
    int v = (t < nb) ? g_bsum[t] : 0;
    int x = v;
#pragma unroll
    for (int o = 1; o < 32; o <<= 1) {
        int y = __shfl_up_sync(0xffffffffu, x, o);
        if (lane >= o) x += y;
    }
    if (lane == 31) sh[w] = x;
    __syncthreads();
    if (w == 0) {
        int y = sh[lane];
#pragma unroll
        for (int o = 1; o < 32; o <<= 1) {
            int z = __shfl_up_sync(0xffffffffu, y, o);
            if (lane >= o) y += z;
        }
        sh[lane] = y;
    }
    __syncthreads();
    int incl = x + ((w == 0) ? 0 : sh[w - 1]);
    if (t < nb) g_bsumx[t] = incl - v;
    if (t == 0) g_off[n] = Etot;
}
__global__ void scan3_k(int n) {               // add block base; init fill cursors
    int i = blockIdx.x * blockDim.x + threadIdx.x;
    if (i < n) {
        int o = g_off[i] + g_bsumx[i >> 10];
        g_off[i] = o;
        g_cnt[i] = o;
    }
}
__global__ void csr_fill_k(const int* __restrict__ ei, int E, int Etot) {
    int i = blockIdx.x * blockDim.x + threadIdx.x;
    if (i >= Etot) return;
    int s, d;
    if (i < E) { s = ei[i]; d = ei[E + i]; }
    else       { s = i - E; d = s; }
    int pos = atomicAdd(&g_cnt[d], 1);
    g_csr[pos] = s;
}

// --------------------- split-bf16 HMMA GEMM (128x64 tile) ------------------
// C[128,64] = A[128,KIN] @ W[KIN, tile*64 .. +64]; segments hi*hi+lo*hi+hi*lo.
// Output stored fp16; epilogue computes attention logits for this tile's head.
template<int KIN, int Hh>
__global__ void __launch_bounds__(256, 1)
gemm_mma_k(const float* __restrict__ a_s, const float* __restrict__ a_d,
           int nrows, int noutTot, int wOff) {
    constexpr int KEXT = 2 * KIN;
    constexpr int SA   = KEXT + 8;            // padded smem stride (elems)
    extern __shared__ __align__(16) __nv_bfloat16 sm[];
    __nv_bfloat16* As = sm;                   // [128][SA]
    __nv_bfloat16* Bs = sm + 128 * SA;        // [64][SA]
    const int tid = threadIdx.x, wid = tid >> 5, lane = tid & 31;
    const int r0 = blockIdx.x * 128;
    const int tl = blockIdx.y;

    constexpr int QA = KEXT / 8;              // uint4 per row
    for (int idx = tid; idx < 128 * QA; idx += 256) {
        int row = idx / QA, q = idx - row * QA;
        uint4 v = make_uint4(0u, 0u, 0u, 0u);
        if (r0 + row < nrows)
            v = ((const uint4*)(g_ext + (size_t)(r0 + row) * KEXT))[q];
        *(uint4*)(As + row * SA + q * 8) = v;
    }
    const __nv_bfloat16* Bg = g_wext + wOff + (size_t)tl * 64 * KEXT;
    for (int idx = tid; idx < 64 * QA; idx += 256) {
        int row = idx / QA, q = idx - row * QA;
        uint4 v = ((const uint4*)(Bg + (size_t)row * KEXT))[q];
        *(uint4*)(Bs + row * SA + q * 8) = v;
    }
    __syncthreads();

    const int g  = lane >> 2, tq = lane & 3;
    const int mr = wid * 16;
    float c[8][4];
#pragma unroll
    for (int j = 0; j < 8; j++)
#pragma unroll
        for (int i = 0; i < 4; i++) c[j][i] = 0.f;

    // ldmatrix base addresses
    const int mi = lane >> 3;
    const uint32_t baseA = (uint32_t)__cvta_generic_to_shared(As)
        + ((mr + (lane & 7) + (mi & 1) * 8) * SA + (mi >> 1) * 8) * 2;
    uint32_t baseB[8];
#pragma unroll
    for (int j = 0; j < 8; j++)
        baseB[j] = (uint32_t)__cvta_generic_to_shared(Bs)
            + ((j * 8 + (lane & 7)) * SA + ((lane >> 3) & 1) * 8) * 2;

#pragma unroll
    for (int sg = 0; sg < 3; sg++) {
        const int ak0 = (sg == 1) ? KIN : 0;
        const int bk0 = (sg == 2) ? KIN : 0;
#pragma unroll 2
        for (int ks = 0; ks < KIN / 16; ks++) {
            uint32_t a0, a1, a2, a3;
            ldsm_x4(a0, a1, a2, a3, baseA + (ak0 + ks * 16) * 2);
#pragma unroll
            for (int j = 0; j < 8; j++) {
                uint32_t b0, b1;
                ldsm_x2(b0, b1, baseB[j] + (bk0 + ks * 16) * 2);
                asm volatile(
                    "mma.sync.aligned.m16n8k16.row.col.f32.bf16.bf16.f32 "
                    "{%0,%1,%2,%3}, {%4,%5,%6,%7}, {%8,%9}, {%0,%1,%2,%3};"
                    : "+f"(c[j][0]), "+f"(c[j][1]), "+f"(c[j][2]), "+f"(c[j][3])
                    : "r"(a0), "r"(a1), "r"(a2), "r"(a3), "r"(b0), "r"(b1));
            }
        }
    }

    // store fp16
    __half* g_h16 = (__half*)g_h;
    const int gr0 = r0 + mr + g, gr1 = gr0 + 8;
    if (gr0 < nrows) {
        __half* H0 = g_h16 + (size_t)gr0 * noutTot + tl * 64 + tq * 2;
#pragma unroll
        for (int j = 0; j < 8; j++)
            *(__half2*)(H0 + j * 8) = __floats2half2_rn(c[j][0], c[j][1]);
    }
    if (gr1 < nrows) {
        __half* H1 = g_h16 + (size_t)gr1 * noutTot + tl * 64 + tq * 2;
#pragma unroll
        for (int j = 0; j < 8; j++)
            *(__half2*)(H1 + j * 8) = __floats2half2_rn(c[j][2], c[j][3]);
    }

    // fused attention logits: row dot a_s / a_d for head `tl` (fp32 regs)
    float s0 = 0.f, d0 = 0.f, s1 = 0.f, d1 = 0.f;
#pragma unroll
    for (int j = 0; j < 8; j++) {
        int cc = j * 8 + tq * 2;
        float av0 = __ldg(a_s + tl * 64 + cc), av1 = __ldg(a_s + tl * 64 + cc + 1);
        float bv0 = __ldg(a_d + tl * 64 + cc), bv1 = __ldg(a_d + tl * 64 + cc + 1);
        s0 += c[j][0] * av0 + c[j][1] * av1;
        d0 += c[j][0] * bv0 + c[j][1] * bv1;
        s1 += c[j][2] * av0 + c[j][3] * av1;
        d1 += c[j][2] * bv0 + c[j][3] * bv1;
    }
#pragma unroll
    for (int o = 1; o <= 2; o <<= 1) {
        s0 += __shfl_xor_sync(0xffffffffu, s0, o);
        d0 += __shfl_xor_sync(0xffffffffu, d0, o);
        s1 += __shfl_xor_sync(0xffffffffu, s1, o);
        d1 += __shfl_xor_sync(0xffffffffu, d1, o);
    }
    if (tq == 0) {
        if (gr0 < nrows) { g_als[gr0 * Hh + tl] = s0; g_ald[gr0 * Hh + tl] = d0; }
        if (gr1 < nrows) { g_als[gr1 * Hh + tl] = s1; g_ald[gr1 * Hh + tl] = d1; }
    }
}

// ------------- fused per-dst single-pass softmax aggregation ---------------
// One warp per dst; lane owns V = HOUT/32 contiguous channels; h is fp16.
// 4x unrolled edge loop: 4 h-gathers in flight (MLP=4), csr prefetched one
// iteration ahead, exp lane-parallel on lanes j*Hh+h (j<4). No max pass.
// MODE 0: write hi|lo bf16 ext (next GEMM input). MODE 1: fp32 out + g_cnt=0.
template<int HOUT, int Hh, int MODE>
__global__ void aggr_k(const float* __restrict__ bias, float* __restrict__ outp, int n) {
    const int warp = (blockIdx.x * blockDim.x + threadIdx.x) >> 5;
    const int lane = threadIdx.x & 31;
    if (warp >= n) return;
    const int dst = warp;
    const int beg = g_off[dst], end = g_off[dst + 1];
    constexpr int V = HOUT / 32;
    const __half* g_h16 = (const __half*)g_h;

    float ald_own;                            // aldd[lane&3] (valid on all lanes)
    if (Hh == 4) {
        float4 t = *(const float4*)(g_ald + dst * 4);
        ald_own = (lane & 2) ? ((lane & 1) ? t.w : t.z)
                             : ((lane & 1) ? t.y : t.x);
    } else ald_own = g_ald[dst];

    float acc[V];
#pragma unroll
    for (int k = 0; k < V; k++) acc[k] = 0.f;
    float den = 0.f;
    const int headL = (Hh == 1) ? 0 : (lane >> 3);

    int e = beg;
    int s0 = 0, s1 = 0, s2 = 0, s3 = 0;
    if (e + 4 <= end) {
        s0 = g_csr[e]; s1 = g_csr[e + 1]; s2 = g_csr[e + 2]; s3 = g_csr[e + 3];
    }
    while (e + 4 <= end) {
        int n0 = 0, n1 = 0, n2 = 0, n3 = 0;
        if (e + 8 <= end) {
            n0 = g_csr[e + 4]; n1 = g_csr[e + 5]; n2 = g_csr[e + 6]; n3 = g_csr[e + 7];
        }
        // lane = j*Hh + h for j<4, h<Hh computes exp of (edge j, head h)
        float exh = 0.f;
        if (lane < 4 * Hh) {
            int j  = (Hh == 4) ? (lane >> 2) : lane;
            int ss = (j & 2) ? ((j & 1) ? s3 : s2) : ((j & 1) ? s1 : s0);
            int hh = (Hh == 4) ? (lane & 3) : 0;
            float v = g_als[ss * Hh + hh] + ald_own;
            v = v > 0.f ? v : 0.2f * v;
            exh = __expf(v);
            den += exh;
        }
        float ex0 = __shfl_sync(0xffffffffu, exh, 0 * Hh + headL);
        float ex1 = __shfl_sync(0xffffffffu, exh, 1 * Hh + headL);
        float ex2 = __shfl_sync(0xffffffffu, exh, 2 * Hh + headL);
        float ex3 = __shfl_sync(0xffffffffu, exh, 3 * Hh + headL);
        if (V == 8) {
            uint4 p0 = ((const uint4*)(g_h16 + (size_t)s0 * HOUT))[lane];
            uint4 p1 = ((const uint4*)(g_h16 + (size_t)s1 * HOUT))[lane];
            uint4 p2 = ((const uint4*)(g_h16 + (size_t)s2 * HOUT))[lane];
            uint4 p3 = ((const uint4*)(g_h16 + (size_t)s3 * HOUT))[lane];
#define ACC8(P, EX) { \
            float2 f0 = __half22float2(*(__half2*)&(P).x); \
            float2 f1 = __half22float2(*(__half2*)&(P).y); \
            float2 f2 = __half22float2(*(__half2*)&(P).z); \
            float2 f3 = __half22float2(*(__half2*)&(P).w); \
            acc[0] += (EX) * f0.x; acc[1] += (EX) * f0.y; \
            acc[2] += (EX) * f1.x; acc[3] += (EX) * f1.y; \
            acc[4] += (EX) * f2.x; acc[5] += (EX) * f2.y; \
            acc[6] += (EX) * f3.x; acc[7] += (EX) * f3.y; }
            ACC8(p0, ex0) ACC8(p1, ex1) ACC8(p2, ex2) ACC8(p3, ex3)
        } else {
            uint32_t p0 = ((const uint32_t*)(g_h16 + (size_t)s0 * HOUT))[lane];
            uint32_t p1 = ((const uint32_t*)(g_h16 + (size_t)s1 * HOUT))[lane];
            uint32_t p2 = ((const uint32_t*)(g_h16 + (size_t)s2 * HOUT))[lane];
            uint32_t p3 = ((const uint32_t*)(g_h16 + (size_t)s3 * HOUT))[lane];
            float2 f0 = __half22float2(*(__half2*)&p0);
            float2 f1 = __half22float2(*(__half2*)&p1);
            float2 f2 = __half22float2(*(__half2*)&p2);
            float2 f3 = __half22float2(*(__half2*)&p3);
            acc[0] += ex0 * f0.x; acc[1] += ex0 * f0.y;
            acc[0] += ex1 * f1.x; acc[1] += ex1 * f1.y;
            acc[0] += ex2 * f2.x; acc[1] += ex2 * f2.y;
            acc[0] += ex3 * f3.x; acc[1] += ex3 * f3.y;
        }
        e += 4; s0 = n0; s1 = n1; s2 = n2; s3 = n3;
    }
    // tail (deg%4 edges): original per-edge path on lanes 0..Hh-1
    for (; e < end; e++) {
        int s = g_csr[e];
        float exh = 0.f;
        if (lane < Hh) {
            float v = g_als[s * Hh + lane] + ald_own;
            v = v > 0.f ? v : 0.2f * v;
            exh = __expf(v);
            den += exh;
        }
        float ex = __shfl_sync(0xffffffffu, exh, headL);
        if (V == 8) {
            uint4 p = ((const uint4*)(g_h16 + (size_t)s * HOUT))[lane];
            ACC8(p, ex)
        } else {
            uint32_t p = ((const uint32_t*)(g_h16 + (size_t)s * HOUT))[lane];
            float2 f = __half22float2(*(__half2*)&p);
            acc[0] += ex * f.x; acc[1] += ex * f.y;
        }
    }

    // denominator: distributed over lanes j*Hh+h (j<4); tail went into j=0 lanes
    float dv = __shfl_sync(0xffffffffu, den, 0 * Hh + headL)
             + __shfl_sync(0xffffffffu, den, 1 * Hh + headL)
             + __shfl_sync(0xffffffffu, den, 2 * Hh + headL)
             + __shfl_sync(0xffffffffu, den, 3 * Hh + headL);
    float inv = 1.f / (dv + 1e-16f);
    float r[V];
    if (V == 8) {
        float4 b0 = *(const float4*)(bias + lane * 8);
        float4 b1 = *(const float4*)(bias + lane * 8 + 4);
        r[0] = acc[0] * inv + b0.x; r[1] = acc[1] * inv + b0.y;
        r[2] = acc[2] * inv + b0.z; r[3] = acc[3] * inv + b0.w;
        r[4] = acc[4] * inv + b1.x; r[5] = acc[5] * inv + b1.y;
        r[6] = acc[6] * inv + b1.z; r[7] = acc[7] * inv + b1.w;
    } else {
        float2 b = *(const float2*)(bias + lane * 2);
        r[0] = acc[0] * inv + b.x; r[1] = acc[1] * inv + b.y;
    }
#pragma unroll
    for (int j = 0; j < V; j++) r[j] = r[j] > 0.f ? r[j] : expm1f(r[j]);

    if (MODE == 1) {
        if (V == 2)
            *(float2*)(outp + (size_t)dst * HOUT + lane * 2) = make_float2(r[0], r[1]);
        if (lane == 0) g_cnt[dst] = 0;       // reset cursors for next replay
    } else {
        __nv_bfloat16 hi[V], lo[V];
#pragma unroll
        for (int j = 0; j < V; j++) {
            hi[j] = __float2bfloat16_rn(r[j]);
            lo[j] = __float2bfloat16_rn(r[j] - __bfloat162float(hi[j]));
        }
        if (V == 8) {
            __nv_bfloat16* eb = g_ext + (size_t)dst * 512 + lane * 8;
            *(uint4*)eb         = make_uint4(pk(hi[0], hi[1]), pk(hi[2], hi[3]),
                                             pk(hi[4], hi[5]), pk(hi[6], hi[7]));
            *(uint4*)(eb + 256) = make_uint4(pk(lo[0], lo[1]), pk(lo[2], lo[3]),
                                             pk(lo[4], lo[5]), pk(lo[6], lo[7]));
        } else {
            __nv_bfloat16* eb = g_ext + (size_t)dst * 128 + lane * 2;
            *(uint32_t*)eb        = pk(hi[0], hi[1]);
            *(uint32_t*)(eb + 64) = pk(lo[0], lo[1]);
        }
    }
}

// ---------------------------------------------------------------------------
extern "C" void kernel_launch(void* const* d_in, const int* in_sizes, int n_in,
                              void* d_out, int out_size) {
    const float* x   = (const float*)d_in[0];
    const int*   ei  = (const int*)  d_in[1];
    const float* W0  = (const float*)d_in[2];
    const float* as0 = (const float*)d_in[3];
    const float* ad0 = (const float*)d_in[4];
    const float* b0  = (const float*)d_in[5];
    const float* W1  = (const float*)d_in[6];
    const float* as1 = (const float*)d_in[7];
    const float* ad1 = (const float*)d_in[8];
    const float* b1  = (const float*)d_in[9];
    const float* W2  = (const float*)d_in[10];
    const float* as2 = (const float*)d_in[11];
    const float* ad2 = (const float*)d_in[12];
    const float* b2  = (const float*)d_in[13];
    float* out = (float*)d_out;

    const int n    = in_sizes[0] / INCH;   // 50000
    const int E    = in_sizes[1] / 2;      // 800000
    const int Etot = E + n;

    const int SM256 = (128 + 64) * (512 + 8) * 2;   // 199,680 B
    const int SM64  = (128 + 64) * (128 + 8) * 2;   //  52,224 B
    cudaFuncSetAttribute((const void*)gemm_mma_k<256, 4>, cudaFuncAttributeMaxDynamicSharedMemorySize, SM256);
    cudaFuncSetAttribute((const void*)gemm_mma_k<256, 1>, cudaFuncAttributeMaxDynamicSharedMemorySize, SM256);
    cudaFuncSetAttribute((const void*)gemm_mma_k<64, 1>,  cudaFuncAttributeMaxDynamicSharedMemorySize, SM64);

    // ---- prep (count + x ext + W ext), parallel scan, fill ----
    const int prepTot = Etot + n * 64 + 32768 + 8192 + 2048;
    prep_k<<<cdiv(prepTot, 256), 256>>>(x, ei, W0, W1, W2, n, E, Etot);
    const int nb1 = cdiv(n, 1024);
    scan1_k<<<nb1, 1024>>>(n);
    scan2_k<<<1, 1024>>>(nb1, n, Etot);
    scan3_k<<<cdiv(n, 256), 256>>>(n);
    csr_fill_k<<<cdiv(Etot, 256), 256>>>(ei, E, Etot);

    const int nb = cdiv(n, 128);

    // ---- Layer 0: 256 -> 4x64 concat ----
    gemm_mma_k<256, 4><<<dim3(nb, 4), 256, SM256>>>(as0, ad0, n, 256, WOFF0);
    aggr_k<256, 4, 0><<<cdiv(n * 32, 256), 256>>>(b0, out, n);

    // ---- Layer 1: 256 -> 64 ----
    gemm_mma_k<256, 1><<<dim3(nb, 1), 256, SM256>>>(as1, ad1, n, 64, WOFF1);
    aggr_k<64, 1, 0><<<cdiv(n * 32, 256), 256>>>(b1, out, n);

    // ---- Layer 2: 64 -> 64 ----
    gemm_mma_k<64, 1><<<dim3(nb, 1), 256, SM64>>>(as2, ad2, n, 64, WOFF2);
    aggr_k<64, 1, 1><<<cdiv(n * 32, 256), 256>>>(b2, out, n);
}

// round 13
// speedup vs baseline: 3.7720x; 1.0013x over previous
#include <cuda_runtime.h>
#include <cuda_bf16.h>
#include <cuda_fp16.h>
#include <math_constants.h>
#include <cstdint>

// ---------------------------------------------------------------------------
// ModifiedGAT: 3-layer GAT (PyG GATConv, add_self_loops=True)
//   L0: 256 -> 4x64 concat=256, ELU;  L1: 256 -> 64, ELU;  L2: 64 -> 64, ELU
// CSR-gather single-pass-softmax aggregation (fp16 h, deep-MLP unrolled) +
// split-bf16 HMMA GEMMs (ldmatrix) with fused logits epilogue + fused fill.
// ---------------------------------------------------------------------------

#define NMAX   50000
#define EMAX   850000
#define INCH   256
#define OUTC   64

__device__ float g_h   [NMAX * 128];           // GEMM output, stored as __half (256 ch max)
__device__ float g_als [NMAX * 4];
__device__ float g_ald [NMAX * 4];
__device__ int   g_cnt [NMAX];                 // statically 0; re-zeroed by last aggr
__device__ int   g_off [NMAX + 1];
__device__ int   g_csr [EMAX];
__device__ int   g_bsum [64];
__device__ int   g_bsumx[64];
__device__ __nv_bfloat16 g_ext [NMAX * 512];   // hi|lo bf16 GEMM input (stride 2*KIN)
__device__ __nv_bfloat16 g_wext[172032];       // W0 | W1 | W2 (hi|lo, [n][kext])

#define WOFF0 0
#define WOFF1 131072
#define WOFF2 163840

static inline int cdiv(int a, int b) { return (a + b - 1) / b; }

__device__ __forceinline__ uint32_t pk(__nv_bfloat16 a, __nv_bfloat16 b) {
    return (uint32_t)__bfloat16_as_ushort(a) | ((uint32_t)__bfloat16_as_ushort(b) << 16);
}
__device__ __forceinline__ void ldsm_x4(uint32_t& r0, uint32_t& r1, uint32_t& r2,
                                        uint32_t& r3, uint32_t addr) {
    asm volatile("ldmatrix.sync.aligned.m8n8.x4.shared.b16 {%0,%1,%2,%3}, [%4];"
                 : "=r"(r0), "=r"(r1), "=r"(r2), "=r"(r3) : "r"(addr));
}
__device__ __forceinline__ void ldsm_x2(uint32_t& r0, uint32_t& r1, uint32_t addr) {
    asm volatile("ldmatrix.sync.aligned.m8n8.x2.shared.b16 {%0,%1}, [%2];"
                 : "=r"(r0), "=r"(r1) : "r"(addr));
}

// ------------------- fused prep: edge count, x-ext, W-ext ------------------
__device__ __forceinline__ void wext_body(const float* __restrict__ W, int stride,
                                          int KIN, int idx, int outOff) {
    int nn   = idx & 63;
    int rest = idx >> 6;
    int kp   = rest % (KIN / 2);
    int t    = rest / (KIN / 2);
    int k0   = kp * 2;
    int col  = t * 64 + nn;
    float w0 = W[(size_t)k0 * stride + col];
    float w1 = W[(size_t)(k0 + 1) * stride + col];
    __nv_bfloat16 h0 = __float2bfloat16_rn(w0);
    __nv_bfloat16 h1 = __float2bfloat16_rn(w1);
    __nv_bfloat16 l0 = __float2bfloat16_rn(w0 - __bfloat162float(h0));
    __nv_bfloat16 l1 = __float2bfloat16_rn(w1 - __bfloat162float(h1));
    __nv_bfloat16* base = g_wext + outOff + ((size_t)t * 64 + nn) * (2 * KIN);
    *(uint32_t*)(base + k0)       = pk(h0, h1);
    *(uint32_t*)(base + KIN + k0) = pk(l0, l1);
}

__global__ void prep_k(const float* __restrict__ x, const int* __restrict__ ei,
                       const float* __restrict__ W0, const float* __restrict__ W1,
                       const float* __restrict__ W2, int n, int E, int Etot) {
    int i = blockIdx.x * blockDim.x + threadIdx.x;
    if (i < Etot) {                            // CSR degree count (g_cnt starts 0)
        int d = (i < E) ? ei[E + i] : (i - E);
        atomicAdd(&g_cnt[d], 1);
        return;
    }
    int j = i - Etot;
    const int extN = n * 64;                   // KIN=256 -> 64 float4 per row
    if (j < extN) {
        int row = j >> 6, q = j & 63;
        float4 v = ((const float4*)x)[j];
        __nv_bfloat16 h0 = __float2bfloat16_rn(v.x), h1 = __float2bfloat16_rn(v.y);
        __nv_bfloat16 h2 = __float2bfloat16_rn(v.z), h3 = __float2bfloat16_rn(v.w);
        __nv_bfloat16 l0 = __float2bfloat16_rn(v.x - __bfloat162float(h0));
        __nv_bfloat16 l1 = __float2bfloat16_rn(v.y - __bfloat162float(h1));
        __nv_bfloat16 l2 = __float2bfloat16_rn(v.z - __bfloat162float(h2));
        __nv_bfloat16 l3 = __float2bfloat16_rn(v.w - __bfloat162float(h3));
        __nv_bfloat16* d = g_ext + (size_t)row * 512 + 4 * q;
        *(uint2*)d         = make_uint2(pk(h0, h1), pk(h2, h3));
        *(uint2*)(d + 256) = make_uint2(pk(l0, l1), pk(l2, l3));
        return;
    }
    j -= extN;
    if (j < 32768) { wext_body(W0, 256, 256, j, WOFF0); return; }
    j -= 32768;
    if (j < 8192)  { wext_body(W1, 64, 256, j, WOFF1); return; }
    j -= 8192;
    if (j < 2048)  { wext_body(W2, 64, 64, j, WOFF2); return; }
}

// --------------------------- parallel CSR scan -----------------------------
__global__ void scan1_k(int n) {               // per-1024-block local exclusive scan
    __shared__ int sh[32];
    const int t = threadIdx.x, lane = t & 31, w = t >> 5;
    int i = blockIdx.x * 1024 + t;
    int v = (i < n) ? g_cnt[i] : 0;
    int x = v;
#pragma unroll
    for (int o = 1; o < 32; o <<= 1) {
        int y = __shfl_up_sync(0xffffffffu, x, o);
        if (lane >= o) x += y;
    }
    if (lane == 31) sh[w] = x;
    __syncthreads();
    if (w == 0) {
        int y = sh[lane];
#pragma unroll
        for (int o = 1; o < 32; o <<= 1) {
            int z = __shfl_up_sync(0xffffffffu, y, o);
            if (lane >= o) y += z;
        }
        sh[lane] = y;
    }
    __syncthreads();
    int incl = x + ((w == 0) ? 0 : sh[w - 1]);
    if (i < n) g_off[i] = incl - v;
    if (t == 1023) g_bsum[blockIdx.x] = incl;
}
__global__ void scan2_k(int nb, int n, int Etot) {  // scan of block sums
    __shared__ int sh[32];
    const int t = threadIdx.x, lane = t & 31, w = t >> 5;
    int v = (t < nb) ? g_bsum[t] : 0;
    int x = v;
#pragma unroll
    for (int o = 1; o < 32; o <<= 1) {
        int y = __shfl_up_sync(0xffffffffu, x, o);
        if (lane >= o) x += y;
    }
    if (lane == 31) sh[w] = x;
    __syncthreads();
    if (w == 0) {
        int y = sh[lane];
#pragma unroll
        for (int o = 1; o < 32; o <<= 1) {
            int z = __shfl_up_sync(0xffffffffu, y, o);
            if (lane >= o) y += z;
        }
        sh[lane] = y;
    }
    __syncthreads();
    int incl = x + ((w == 0) ? 0 : sh[w - 1]);
    if (t < nb) g_bsumx[t] = incl - v;
    if (t == 0) g_off[n] = Etot;
}
__global__ void scan3_k(int n) {               // add block base; init fill cursors
    int i = blockIdx.x * blockDim.x + threadIdx.x;
    if (i < n) {
        int o = g_off[i] + g_bsumx[i >> 10];
        g_off[i] = o;
        g_cnt[i] = o;
    }
}

// --------------------- split-bf16 HMMA GEMM (128x64 tile) ------------------
// C[128,64] = A[128,KIN] @ W[KIN, tile*64 .. +64]; segments hi*hi+lo*hi+hi*lo.
// Output fp16; epilogue computes attention logits. DOFILL: y==0 blocks run the
// CSR fill scatter after their tile (overlaps other blocks' MMA work).
template<int KIN, int Hh, bool DOFILL>
__global__ void __launch_bounds__(256, 1)
gemm_mma_k(const float* __restrict__ a_s, const float* __restrict__ a_d,
           int nrows, int noutTot, int wOff,
           const int* __restrict__ ei, int E, int Etot, int nbx) {
    constexpr int KEXT = 2 * KIN;
    constexpr int SA   = KEXT + 8;            // padded smem stride (elems)
    extern __shared__ __align__(16) __nv_bfloat16 sm[];
    __nv_bfloat16* As = sm;                   // [128][SA]
    __nv_bfloat16* Bs = sm + 128 * SA;        // [64][SA]
    const int tid = threadIdx.x, wid = tid >> 5, lane = tid & 31;
    const int r0 = blockIdx.x * 128;
    const int tl = blockIdx.y;

    constexpr int QA = KEXT / 8;              // uint4 per row
    for (int idx = tid; idx < 128 * QA; idx += 256) {
        int row = idx / QA, q = idx - row * QA;
        uint4 v = make_uint4(0u, 0u, 0u, 0u);
        if (r0 + row < nrows)
            v = ((const uint4*)(g_ext + (size_t)(r0 + row) * KEXT))[q];
        *(uint4*)(As + row * SA + q * 8) = v;
    }
    const __nv_bfloat16* Bg = g_wext + wOff + (size_t)tl * 64 * KEXT;
    for (int idx = tid; idx < 64 * QA; idx += 256) {
        int row = idx / QA, q = idx - row * QA;
        uint4 v = ((const uint4*)(Bg + (size_t)row * KEXT))[q];
        *(uint4*)(Bs + row * SA + q * 8) = v;
    }
    __syncthreads();

    const int g  = lane >> 2, tq = lane & 3;
    const int mr = wid * 16;
    float c[8][4];
#pragma unroll
    for (int j = 0; j < 8; j++)
#pragma unroll
        for (int i = 0; i < 4; i++) c[j][i] = 0.f;

    // ldmatrix base addresses
    const int mi = lane >> 3;
    const uint32_t baseA = (uint32_t)__cvta_generic_to_shared(As)
        + ((mr + (lane & 7) + (mi & 1) * 8) * SA + (mi >> 1) * 8) * 2;
    uint32_t baseB[8];
#pragma unroll
    for (int j = 0; j < 8; j++)
        baseB[j] = (uint32_t)__cvta_generic_to_shared(Bs)
            + ((j * 8 + (lane & 7)) * SA + ((lane >> 3) & 1) * 8) * 2;

#pragma unroll
    for (int sg = 0; sg < 3; sg++) {
        const int ak0 = (sg == 1) ? KIN : 0;
        const int bk0 = (sg == 2) ? KIN : 0;
#pragma unroll 2
        for (int ks = 0; ks < KIN / 16; ks++) {
            uint32_t a0, a1, a2, a3;
            ldsm_x4(a0, a1, a2, a3, baseA + (ak0 + ks * 16) * 2);
#pragma unroll
            for (int j = 0; j < 8; j++) {
                uint32_t b0, b1;
                ldsm_x2(b0, b1, baseB[j] + (bk0 + ks * 16) * 2);
                asm volatile(
                    "mma.sync.aligned.m16n8k16.row.col.f32.bf16.bf16.f32 "
                    "{%0,%1,%2,%3}, {%4,%5,%6,%7}, {%8,%9}, {%0,%1,%2,%3};"
                    : "+f"(c[j][0]), "+f"(c[j][1]), "+f"(c[j][2]), "+f"(c[j][3])
                    : "r"(a0), "r"(a1), "r"(a2), "r"(a3), "r"(b0), "r"(b1));
            }
        }
    }

    // store fp16
    __half* g_h16 = (__half*)g_h;
    const int gr0 = r0 + mr + g, gr1 = gr0 + 8;
    if (gr0 < nrows) {
        __half* H0 = g_h16 + (size_t)gr0 * noutTot + tl * 64 + tq * 2;
#pragma unroll
        for (int j = 0; j < 8; j++)
            *(__half2*)(H0 + j * 8) = __floats2half2_rn(c[j][0], c[j][1]);
    }
    if (gr1 < nrows) {
        __half* H1 = g_h16 + (size_t)gr1 * noutTot + tl * 64 + tq * 2;
#pragma unroll
        for (int j = 0; j < 8; j++)
            *(__half2*)(H1 + j * 8) = __floats2half2_rn(c[j][2], c[j][3]);
    }

    // fused attention logits: row dot a_s / a_d for head `tl` (fp32 regs)
    float s0 = 0.f, d0 = 0.f, s1 = 0.f, d1 = 0.f;
#pragma unroll
    for (int j = 0; j < 8; j++) {
        int cc = j * 8 + tq * 2;
        float av0 = __ldg(a_s + tl * 64 + cc), av1 = __ldg(a_s + tl * 64 + cc + 1);
        float bv0 = __ldg(a_d + tl * 64 + cc), bv1 = __ldg(a_d + tl * 64 + cc + 1);
        s0 += c[j][0] * av0 + c[j][1] * av1;
        d0 += c[j][0] * bv0 + c[j][1] * bv1;
        s1 += c[j][2] * av0 + c[j][3] * av1;
        d1 += c[j][2] * bv0 + c[j][3] * bv1;
    }
#pragma unroll
    for (int o = 1; o <= 2; o <<= 1) {
        s0 += __shfl_xor_sync(0xffffffffu, s0, o);
        d0 += __shfl_xor_sync(0xffffffffu, d0, o);
        s1 += __shfl_xor_sync(0xffffffffu, s1, o);
        d1 += __shfl_xor_sync(0xffffffffu, d1, o);
    }
    if (tq == 0) {
        if (gr0 < nrows) { g_als[gr0 * Hh + tl] = s0; g_ald[gr0 * Hh + tl] = d0; }
        if (gr1 < nrows) { g_als[gr1 * Hh + tl] = s1; g_ald[gr1 * Hh + tl] = d1; }
    }

    // fused CSR fill (y==0 blocks only), overlaps other blocks' GEMM work
    if (DOFILL && blockIdx.y == 0) {
        const int stride = nbx * 256;
        for (int i = blockIdx.x * 256 + tid; i < Etot; i += stride) {
            int s, d;
            if (i < E) { s = ei[i]; d = ei[E + i]; }
            else       { s = i - E; d = s; }
            int pos = atomicAdd(&g_cnt[d], 1);
            g_csr[pos] = s;
        }
    }
}

// ------------- fused per-dst single-pass softmax aggregation ---------------
// One warp per dst; lane owns V = HOUT/32 contiguous channels; h is fp16.
// UN-deep unroll (4 for V==8, 8 for V==2): UN h-gathers in flight, csr
// prefetched one iteration ahead, exp lane-parallel on lanes j*Hh+h (j<UN).
// MODE 0: write hi|lo bf16 ext (next GEMM input). MODE 1: fp32 out + g_cnt=0.
template<int HOUT, int Hh, int MODE>
__global__ void aggr_k(const float* __restrict__ bias, float* __restrict__ outp, int n) {
    const int warp = (blockIdx.x * blockDim.x + threadIdx.x) >> 5;
    const int lane = threadIdx.x & 31;
    if (warp >= n) return;
    const int dst = warp;
    const int beg = g_off[dst], end = g_off[dst + 1];
    constexpr int V  = HOUT / 32;
    constexpr int UN = (V == 8) ? 4 : 8;
    const __half* g_h16 = (const __half*)g_h;

    float ald_own;                            // aldd[lane&3] (valid on all lanes)
    if (Hh == 4) {
        float4 t = *(const float4*)(g_ald + dst * 4);
        ald_own = (lane & 2) ? ((lane & 1) ? t.w : t.z)
                             : ((lane & 1) ? t.y : t.x);
    } else ald_own = g_ald[dst];

    float acc[V];
#pragma unroll
    for (int k = 0; k < V; k++) acc[k] = 0.f;
    float den = 0.f;
    const int headL = (Hh == 1) ? 0 : (lane >> 3);

    int e = beg;
    int s[UN];
#pragma unroll
    for (int j = 0; j < UN; j++) s[j] = 0;
    if (e + UN <= end) {
#pragma unroll
        for (int j = 0; j < UN; j++) s[j] = g_csr[e + j];
    }
    while (e + UN <= end) {
        int ns[UN];
#pragma unroll
        for (int j = 0; j < UN; j++) ns[j] = 0;
        if (e + 2 * UN <= end) {
#pragma unroll
            for (int j = 0; j < UN; j++) ns[j] = g_csr[e + UN + j];
        }
        // lane = j*Hh + h for j<UN, h<Hh computes exp of (edge j, head h)
        float exh = 0.f;
        if (lane < UN * Hh) {
            int ss;
            if (Hh == 4) {                     // UN=4, j = lane>>2
                int j = lane >> 2;
                ss = (j & 2) ? ((j & 1) ? s[3] : s[2]) : ((j & 1) ? s[1] : s[0]);
            } else {                           // UN=8, j = lane
                int t0 = (lane & 1) ? s[1] : s[0];
                int t1 = (lane & 1) ? s[3] : s[2];
                int t2 = (lane & 1) ? s[5] : s[4];
                int t3 = (lane & 1) ? s[7 % UN] : s[6 % UN];
                int u0 = (lane & 2) ? t1 : t0;
                int u1 = (lane & 2) ? t3 : t2;
                ss = (lane & 4) ? u1 : u0;
            }
            int hh = (Hh == 4) ? (lane & 3) : 0;
            float v = g_als[ss * Hh + hh] + ald_own;
            v = v > 0.f ? v : 0.2f * v;
            exh = __expf(v);
            den += exh;
        }
        if (V == 8) {
            float ex0 = __shfl_sync(0xffffffffu, exh, 0 * Hh + headL);
            float ex1 = __shfl_sync(0xffffffffu, exh, 1 * Hh + headL);
            float ex2 = __shfl_sync(0xffffffffu, exh, 2 * Hh + headL);
            float ex3 = __shfl_sync(0xffffffffu, exh, 3 * Hh + headL);
            uint4 p0 = ((const uint4*)(g_h16 + (size_t)s[0] * HOUT))[lane];
            uint4 p1 = ((const uint4*)(g_h16 + (size_t)s[1] * HOUT))[lane];
            uint4 p2 = ((const uint4*)(g_h16 + (size_t)s[2] * HOUT))[lane];
            uint4 p3 = ((const uint4*)(g_h16 + (size_t)s[3] * HOUT))[lane];
#define ACC8(P, EX) { \
            float2 f0 = __half22float2(*(__half2*)&(P).x); \
            float2 f1 = __half22float2(*(__half2*)&(P).y); \
            float2 f2 = __half22float2(*(__half2*)&(P).z); \
            float2 f3 = __half22float2(*(__half2*)&(P).w); \
            acc[0] += (EX) * f0.x; acc[1] += (EX) * f0.y; \
            acc[2] += (EX) * f1.x; acc[3] += (EX) * f1.y; \
            acc[4] += (EX) * f2.x; acc[5] += (EX) * f2.y; \
            acc[6] += (EX) * f3.x; acc[7] += (EX) * f3.y; }
            ACC8(p0, ex0) ACC8(p1, ex1) ACC8(p2, ex2) ACC8(p3, ex3)
        } else {
            uint32_t p[UN];
#pragma unroll
            for (int j = 0; j < UN; j++)
                p[j] = ((const uint32_t*)(g_h16 + (size_t)s[j] * HOUT))[lane];
#pragma unroll
            for (int j = 0; j < UN; j++) {
                float ex = __shfl_sync(0xffffffffu, exh, j);
                float2 f = __half22float2(*(__half2*)&p[j]);
                acc[0] += ex * f.x; acc[1] += ex * f.y;
            }
        }
        e += UN;
#pragma unroll
        for (int j = 0; j < UN; j++) s[j] = ns[j];
    }
    // tail (deg%UN edges): per-edge path on lanes 0..Hh-1
    for (; e < end; e++) {
        int ss = g_csr[e];
        float exh = 0.f;
        if (lane < Hh) {
            float v = g_als[ss * Hh + lane] + ald_own;
            v = v > 0.f ? v : 0.2f * v;
            exh = __expf(v);
            den += exh;
        }
        float ex = __shfl_sync(0xffffffffu, exh, headL);
        if (V == 8) {
            uint4 p = ((const uint4*)(g_h16 + (size_t)ss * HOUT))[lane];
            ACC8(p, ex)
        } else {
            uint32_t p = ((const uint32_t*)(g_h16 + (size_t)ss * HOUT))[lane];
            float2 f = __half22float2(*(__half2*)&p);
            acc[0] += ex * f.x; acc[1] += ex * f.y;
        }
    }

    // denominator: distributed over lanes j*Hh+headL (j<UN); tail in j=0 lanes
    float dv = 0.f;
#pragma unroll
    for (int j = 0; j < UN; j++)
        dv += __shfl_sync(0xffffffffu, den, j * Hh + headL);
    float inv = 1.f / (dv + 1e-16f);
    float r[V];
    if (V == 8) {
        float4 b0 = *(const float4*)(bias + lane * 8);
        float4 b1 = *(const float4*)(bias + lane * 8 + 4);
        r[0] = acc[0] * inv + b0.x; r[1] = acc[1] * inv + b0.y;
        r[2] = acc[2] * inv + b0.z; r[3] = acc[3] * inv + b0.w;
        r[4] = acc[4] * inv + b1.x; r[5] = acc[5] * inv + b1.y;
        r[6] = acc[6] * inv + b1.z; r[7] = acc[7] * inv + b1.w;
    } else {
        float2 b = *(const float2*)(bias + lane * 2);
        r[0] = acc[0] * inv + b.x; r[1] = acc[1] * inv + b.y;
    }
#pragma unroll
    for (int j = 0; j < V; j++) r[j] = r[j] > 0.f ? r[j] : expm1f(r[j]);

    if (MODE == 1) {
        if (V == 2)
            *(float2*)(outp + (size_t)dst * HOUT + lane * 2) = make_float2(r[0], r[1]);
        if (lane == 0) g_cnt[dst] = 0;       // reset cursors for next replay
    } else {
        __nv_bfloat16 hi[V], lo[V];
#pragma unroll
        for (int j = 0; j < V; j++) {
            hi[j] = __float2bfloat16_rn(r[j]);
            lo[j] = __float2bfloat16_rn(r[j] - __bfloat162float(hi[j]));
        }
        if (V == 8) {
            __nv_bfloat16* eb = g_ext + (size_t)dst * 512 + lane * 8;
            *(uint4*)eb         = make_uint4(pk(hi[0], hi[1]), pk(hi[2], hi[3]),
                                             pk(hi[4], hi[5]), pk(hi[6], hi[7]));
            *(uint4*)(eb + 256) = make_uint4(pk(lo[0], lo[1]), pk(lo[2], lo[3]),
                                             pk(lo[4], lo[5]), pk(lo[6], lo[7]));
        } else {
            __nv_bfloat16* eb = g_ext + (size_t)dst * 128 + lane * 2;
            *(uint32_t*)eb        = pk(hi[0], hi[1]);
            *(uint32_t*)(eb + 64) = pk(lo[0], lo[1]);
        }
    }
}

// ---------------------------------------------------------------------------
extern "C" void kernel_launch(void* const* d_in, const int* in_sizes, int n_in,
                              void* d_out, int out_size) {
    const float* x   = (const float*)d_in[0];
    const int*   ei  = (const int*)  d_in[1];
    const float* W0  = (const float*)d_in[2];
    const float* as0 = (const float*)d_in[3];
    const float* ad0 = (const float*)d_in[4];
    const float* b0  = (const float*)d_in[5];
    const float* W1  = (const float*)d_in[6];
    const float* as1 = (const float*)d_in[7];
    const float* ad1 = (const float*)d_in[8];
    const float* b1  = (const float*)d_in[9];
    const float* W2  = (const float*)d_in[10];
    const float* as2 = (const float*)d_in[11];
    const float* ad2 = (const float*)d_in[12];
    const float* b2  = (const float*)d_in[13];
    float* out = (float*)d_out;

    const int n    = in_sizes[0] / INCH;   // 50000
    const int E    = in_sizes[1] / 2;      // 800000
    const int Etot = E + n;

    const int SM256 = (128 + 64) * (512 + 8) * 2;   // 199,680 B
    const int SM64  = (128 + 64) * (128 + 8) * 2;   //  52,224 B
    cudaFuncSetAttribute((const void*)gemm_mma_k<256, 4, true>,  cudaFuncAttributeMaxDynamicSharedMemorySize, SM256);
    cudaFuncSetAttribute((const void*)gemm_mma_k<256, 1, false>, cudaFuncAttributeMaxDynamicSharedMemorySize, SM256);
    cudaFuncSetAttribute((const void*)gemm_mma_k<64, 1, false>,  cudaFuncAttributeMaxDynamicSharedMemorySize, SM64);

    // ---- prep (count + x ext + W ext), parallel scan ----
    const int prepTot = Etot + n * 64 + 32768 + 8192 + 2048;
    prep_k<<<cdiv(prepTot, 256), 256>>>(x, ei, W0, W1, W2, n, E, Etot);
    const int nb1 = cdiv(n, 1024);
    scan1_k<<<nb1, 1024>>>(n);
    scan2_k<<<1, 1024>>>(nb1, n, Etot);
    scan3_k<<<cdiv(n, 256), 256>>>(n);

    const int nb = cdiv(n, 128);

    // ---- Layer 0: 256 -> 4x64 concat (GEMM + fused CSR fill) ----
    gemm_mma_k<256, 4, true><<<dim3(nb, 4), 256, SM256>>>(as0, ad0, n, 256, WOFF0, ei, E, Etot, nb);
    aggr_k<256, 4, 0><<<cdiv(n, 4), 128>>>(b0, out, n);

    // ---- Layer 1: 256 -> 64 ----
    gemm_mma_k<256, 1, false><<<dim3(nb, 1), 256, SM256>>>(as1, ad1, n, 64, WOFF1, ei, E, Etot, nb);
    aggr_k<64, 1, 0><<<cdiv(n, 4), 128>>>(b1, out, n);

    // ---- Layer 2: 64 -> 64 ----
    gemm_mma_k<64, 1, false><<<dim3(nb, 1), 256, SM64>>>(as2, ad2, n, 64, WOFF2, ei, E, Etot, nb);
    aggr_k<64, 1, 1><<<cdiv(n, 4), 128>>>(b2, out, n);
}